// round 7
// baseline (speedup 1.0000x reference)
#include <cuda_runtime.h>
#include <cstdint>

#define B_    4
#define S_    2048
#define D_    1024
#define H_    16
#define HD_   64
#define MLP_  4096
#define MROWS (B_*S_)   // 8192

// Scratch (device globals — no runtime allocation allowed)
__device__ float g_xn[(size_t)MROWS * D_];
__device__ float g_h [(size_t)MROWS * MLP_];
__device__ float g_q [(size_t)MROWS * D_];
__device__ float g_k [(size_t)MROWS * D_];
__device__ float g_v [(size_t)MROWS * D_];
__device__ float g_av[(size_t)MROWS * D_];

// ---------------------------------------------------------------------------
// RMSNorm: one block per row (1024 elems), 256 threads, float4 per thread
// ---------------------------------------------------------------------------
__global__ __launch_bounds__(256) void rmsnorm_kernel(
    const float* __restrict__ x, const float* __restrict__ scale,
    float* __restrict__ out)
{
    int row = blockIdx.x;
    const float4* xr = (const float4*)(x + (size_t)row * D_);
    float4 v = xr[threadIdx.x];
    float s = v.x*v.x + v.y*v.y + v.z*v.z + v.w*v.w;

    __shared__ float red[256];
    red[threadIdx.x] = s;
    __syncthreads();
    #pragma unroll
    for (int off = 128; off > 0; off >>= 1) {
        if (threadIdx.x < off) red[threadIdx.x] += red[threadIdx.x + off];
        __syncthreads();
    }
    float inv = rsqrtf(red[0] * (1.0f / D_) + 1e-6f);

    float4 sc = ((const float4*)scale)[threadIdx.x];
    float4 o;
    o.x = v.x * inv * sc.x;
    o.y = v.y * inv * sc.y;
    o.z = v.z * inv * sc.z;
    o.w = v.w * inv * sc.w;
    ((float4*)(out + (size_t)row * D_))[threadIdx.x] = o;
}

// ---------------------------------------------------------------------------
// TF32 helpers
// ---------------------------------------------------------------------------
__device__ __forceinline__ uint32_t f2tf(float x) {
    uint32_t r;
    asm("cvt.rna.tf32.f32 %0, %1;" : "=r"(r) : "f"(x));
    return r;
}
// packed split: .x = hi tf32, .y = lo tf32
__device__ __forceinline__ uint2 tf_pk(float v) {
    uint32_t hi = f2tf(v);
    float r = v - __uint_as_float(hi);
    return make_uint2(hi, f2tf(r));
}
__device__ __forceinline__ void mma8(float* c, const uint32_t* a, const uint32_t* b) {
    asm volatile(
        "mma.sync.aligned.m16n8k8.row.col.f32.tf32.tf32.f32 "
        "{%0,%1,%2,%3}, {%4,%5,%6,%7}, {%8,%9}, {%0,%1,%2,%3};"
        : "+f"(c[0]), "+f"(c[1]), "+f"(c[2]), "+f"(c[3])
        : "r"(a[0]), "r"(a[1]), "r"(a[2]), "r"(a[3]), "r"(b[0]), "r"(b[1]));
}

// ---------------------------------------------------------------------------
// Tensor-core GEMM (3xTF32, ~fp32 accuracy). 128x128 tile, BK=16, 256 thr.
// hi/lo split happens ONCE per element at smem-store; smem holds uint2
// (hi,lo) pairs so each fragment element is a single LDS.64.
// Stride 140 uint2/row: the 4(k)x8(m) fragment pattern is conflict-free.
// EPI: 0 = plain, 1 = gelu(tanh), 2 = +bias1+bias2+resid, 3 = += C
// ---------------------------------------------------------------------------
#define TGS 140                                        // uint2 per smem row
#define TG_SMEM_BYTES (2u * 2u * 16u * TGS * 8u)       // 71680

template<int EPI>
__global__ __launch_bounds__(256, 2) void tgemm_kernel(
    const float* __restrict__ A, const float* __restrict__ Bm,
    float* __restrict__ C,
    const float* __restrict__ bias1, const float* __restrict__ bias2,
    const float* __restrict__ resid,
    int M, int N, int K)
{
    extern __shared__ uint2 dsm[];
    uint2* Asm = dsm;                    // [2][16][TGS]
    uint2* Bsm = dsm + 2 * 16 * TGS;     // [2][16][TGS]
#define AS(st,k,m) Asm[((st)*16+(k))*TGS + (m)]
#define BS(st,k,n) Bsm[((st)*16+(k))*TGS + (n)]

    int tid  = threadIdx.x;
    int bm = blockIdx.y, bn = blockIdx.x;
    int warp = tid >> 5, lane = tid & 31;
    int wm = (warp & 3) * 32;          // warp row base in tile
    int wn = (warp >> 2) * 64;         // warp col base in tile
    int g  = lane >> 2, tg = lane & 3;

    // A load mapping: thread covers (row am, k-chunks ak..ak+3 and +8)
    int am = tid & 127;
    int ak = (tid >> 7) * 4;           // 0 or 4
    // B load mapping: thread covers (k rows bk & bk+8, 4 cols)
    int bk  = tid >> 5;                // 0..7
    int bn4 = (tid & 31) * 4;

    const float* Ap = A  + (size_t)(bm * 128 + am) * K + ak;
    const float* Bp = Bm + (size_t)bk * N + bn * 128 + bn4;

    float acc[2][8][4];
    #pragma unroll
    for (int i = 0; i < 2; i++)
        #pragma unroll
        for (int j = 0; j < 8; j++)
            #pragma unroll
            for (int r = 0; r < 4; r++) acc[i][j][r] = 0.0f;

    // prologue: stage 0
    {
        float4 a0 = *(const float4*)(Ap);
        float4 a1 = *(const float4*)(Ap + 8);
        float4 b0 = *(const float4*)(Bp);
        float4 b1 = *(const float4*)(Bp + (size_t)8 * N);
        AS(0, ak+0, am) = tf_pk(a0.x); AS(0, ak+1, am) = tf_pk(a0.y);
        AS(0, ak+2, am) = tf_pk(a0.z); AS(0, ak+3, am) = tf_pk(a0.w);
        AS(0, ak+8, am) = tf_pk(a1.x); AS(0, ak+9, am) = tf_pk(a1.y);
        AS(0, ak+10, am) = tf_pk(a1.z); AS(0, ak+11, am) = tf_pk(a1.w);
        BS(0, bk, bn4+0) = tf_pk(b0.x); BS(0, bk, bn4+1) = tf_pk(b0.y);
        BS(0, bk, bn4+2) = tf_pk(b0.z); BS(0, bk, bn4+3) = tf_pk(b0.w);
        BS(0, bk+8, bn4+0) = tf_pk(b1.x); BS(0, bk+8, bn4+1) = tf_pk(b1.y);
        BS(0, bk+8, bn4+2) = tf_pk(b1.z); BS(0, bk+8, bn4+3) = tf_pk(b1.w);
    }
    __syncthreads();

    int s = 0;
    for (int k0 = 0; k0 < K; k0 += 16) {
        float4 pa0, pa1, pb0, pb1;
        bool pre = (k0 + 16) < K;
        if (pre) {
            const float* Ap2 = Ap + k0 + 16;
            const float* Bp2 = Bp + (size_t)(k0 + 16) * N;
            pa0 = *(const float4*)(Ap2);
            pa1 = *(const float4*)(Ap2 + 8);
            pb0 = *(const float4*)(Bp2);
            pb1 = *(const float4*)(Bp2 + (size_t)8 * N);
        }

        #pragma unroll
        for (int ks = 0; ks < 2; ks++) {
            int kk = ks * 8;
            uint32_t ahi[2][4], alo[2][4];
            #pragma unroll
            for (int i = 0; i < 2; i++) {
                int m0 = wm + i * 16;
                uint2 t;
                t = AS(s, kk+tg,   m0+g);   ahi[i][0] = t.x; alo[i][0] = t.y;
                t = AS(s, kk+tg,   m0+g+8); ahi[i][1] = t.x; alo[i][1] = t.y;
                t = AS(s, kk+tg+4, m0+g);   ahi[i][2] = t.x; alo[i][2] = t.y;
                t = AS(s, kk+tg+4, m0+g+8); ahi[i][3] = t.x; alo[i][3] = t.y;
            }
            #pragma unroll
            for (int j = 0; j < 8; j++) {
                int n0 = wn + j * 8;
                uint2 t0 = BS(s, kk+tg,   n0+g);
                uint2 t1 = BS(s, kk+tg+4, n0+g);
                uint32_t bhi[2] = { t0.x, t1.x };
                uint32_t blo[2] = { t0.y, t1.y };
                #pragma unroll
                for (int i = 0; i < 2; i++) {
                    mma8(acc[i][j], ahi[i], bhi);
                    mma8(acc[i][j], alo[i], bhi);
                    mma8(acc[i][j], ahi[i], blo);
                }
            }
        }

        if (pre) {
            int sn = s ^ 1;
            AS(sn, ak+0, am) = tf_pk(pa0.x); AS(sn, ak+1, am) = tf_pk(pa0.y);
            AS(sn, ak+2, am) = tf_pk(pa0.z); AS(sn, ak+3, am) = tf_pk(pa0.w);
            AS(sn, ak+8, am) = tf_pk(pa1.x); AS(sn, ak+9, am) = tf_pk(pa1.y);
            AS(sn, ak+10, am) = tf_pk(pa1.z); AS(sn, ak+11, am) = tf_pk(pa1.w);
            BS(sn, bk, bn4+0) = tf_pk(pb0.x); BS(sn, bk, bn4+1) = tf_pk(pb0.y);
            BS(sn, bk, bn4+2) = tf_pk(pb0.z); BS(sn, bk, bn4+3) = tf_pk(pb0.w);
            BS(sn, bk+8, bn4+0) = tf_pk(pb1.x); BS(sn, bk+8, bn4+1) = tf_pk(pb1.y);
            BS(sn, bk+8, bn4+2) = tf_pk(pb1.z); BS(sn, bk+8, bn4+3) = tf_pk(pb1.w);
        }
        __syncthreads();
        s ^= 1;
    }

    // epilogue
    #pragma unroll
    for (int i = 0; i < 2; i++) {
        #pragma unroll
        for (int j = 0; j < 8; j++) {
            int row0 = bm * 128 + wm + i * 16 + g;
            int col  = bn * 128 + wn + j * 8 + tg * 2;
            #pragma unroll
            for (int rr = 0; rr < 2; rr++) {
                int row = row0 + rr * 8;
                size_t idx = (size_t)row * N + col;
                #pragma unroll
                for (int cc = 0; cc < 2; cc++) {
                    float val = acc[i][j][rr * 2 + cc];
                    if (EPI == 1) {
                        float t = 0.7978845608028654f *
                                  (val + 0.044715f * val * val * val);
                        val = 0.5f * val * (1.0f + tanhf(t));
                    } else if (EPI == 2) {
                        val += bias1[col + cc] + bias2[col + cc] + resid[idx + cc];
                    } else if (EPI == 3) {
                        val += C[idx + cc];
                    }
                    C[idx + cc] = val;
                }
            }
        }
    }
#undef AS
#undef BS
}

// ---------------------------------------------------------------------------
// Flash attention (fp32). Grid: (S/128, H, B). 128 threads, one query row per
// thread. K/V staged in SMEM in BK=32 tiles; all compute reads are broadcasts.
// ---------------------------------------------------------------------------
__global__ __launch_bounds__(128) void attn_kernel(
    const float* __restrict__ q, const float* __restrict__ k,
    const float* __restrict__ v, float* __restrict__ av)
{
    int h = blockIdx.y, b = blockIdx.z;
    int tid = threadIdx.x;
    int qi = blockIdx.x * 128 + tid;

    __shared__ float Ks[32][64];
    __shared__ float Vs[32][64];

    const float* qptr = q + ((size_t)(b * S_ + qi)) * D_ + h * HD_;
    float4 qr[16];
    #pragma unroll
    for (int i = 0; i < 16; i++) qr[i] = ((const float4*)qptr)[i];

    float4 acc[16];
    #pragma unroll
    for (int i = 0; i < 16; i++) acc[i] = make_float4(0.f, 0.f, 0.f, 0.f);

    float m = -1e30f, l = 0.0f;
    const float scale = 0.125f;  // 1/sqrt(64)

    int r = tid >> 2;
    int c = (tid & 3) * 16;

    for (int kt = 0; kt < S_; kt += 32) {
        __syncthreads();
        {
            const float* kp = k + ((size_t)(b * S_ + kt + r)) * D_ + h * HD_ + c;
            const float* vp = v + ((size_t)(b * S_ + kt + r)) * D_ + h * HD_ + c;
            #pragma unroll
            for (int i = 0; i < 4; i++) {
                *(float4*)&Ks[r][c + 4 * i] = ((const float4*)kp)[i];
                *(float4*)&Vs[r][c + 4 * i] = ((const float4*)vp)[i];
            }
        }
        __syncthreads();

        float s[32];
        float tmax = -1e30f;
        #pragma unroll
        for (int j = 0; j < 32; j++) {
            const float4* kr = (const float4*)Ks[j];
            float d0 = 0.f;
            #pragma unroll
            for (int i = 0; i < 16; i++) {
                float4 kk = kr[i];
                d0 = fmaf(qr[i].x, kk.x, d0);
                d0 = fmaf(qr[i].y, kk.y, d0);
                d0 = fmaf(qr[i].z, kk.z, d0);
                d0 = fmaf(qr[i].w, kk.w, d0);
            }
            s[j] = d0 * scale;
            tmax = fmaxf(tmax, s[j]);
        }

        float mnew = fmaxf(m, tmax);
        float corr = __expf(m - mnew);
        l *= corr;
        #pragma unroll
        for (int i = 0; i < 16; i++) {
            acc[i].x *= corr; acc[i].y *= corr;
            acc[i].z *= corr; acc[i].w *= corr;
        }
        m = mnew;

        #pragma unroll
        for (int j = 0; j < 32; j++) {
            float p = __expf(s[j] - m);
            l += p;
            const float4* vr = (const float4*)Vs[j];
            #pragma unroll
            for (int i = 0; i < 16; i++) {
                float4 vv = vr[i];
                acc[i].x = fmaf(p, vv.x, acc[i].x);
                acc[i].y = fmaf(p, vv.y, acc[i].y);
                acc[i].z = fmaf(p, vv.z, acc[i].z);
                acc[i].w = fmaf(p, vv.w, acc[i].w);
            }
        }
    }

    float invl = 1.0f / l;
    float* op = av + ((size_t)(b * S_ + qi)) * D_ + h * HD_;
    #pragma unroll
    for (int i = 0; i < 16; i++) {
        float4 o;
        o.x = acc[i].x * invl; o.y = acc[i].y * invl;
        o.z = acc[i].z * invl; o.w = acc[i].w * invl;
        ((float4*)op)[i] = o;
    }
}

// ---------------------------------------------------------------------------
// Launch
// ---------------------------------------------------------------------------
extern "C" void kernel_launch(void* const* d_in, const int* in_sizes, int n_in,
                              void* d_out, int out_size)
{
    const float* x          = (const float*)d_in[0];
    const float* pns        = (const float*)d_in[1];
    const float* w_mlp_in   = (const float*)d_in[2];
    const float* wq         = (const float*)d_in[3];
    const float* wk         = (const float*)d_in[4];
    const float* wv         = (const float*)d_in[5];
    const float* w_mlp_out  = (const float*)d_in[6];
    const float* b_mlp_out  = (const float*)d_in[7];
    const float* w_attn_out = (const float*)d_in[8];
    const float* b_attn_out = (const float*)d_in[9];
    float* out = (float*)d_out;

    float *xn, *hbuf, *q, *k, *v, *av;
    cudaGetSymbolAddress((void**)&xn,   g_xn);
    cudaGetSymbolAddress((void**)&hbuf, g_h);
    cudaGetSymbolAddress((void**)&q,    g_q);
    cudaGetSymbolAddress((void**)&k,    g_k);
    cudaGetSymbolAddress((void**)&v,    g_v);
    cudaGetSymbolAddress((void**)&av,   g_av);

    // opt-in to 70KB dynamic smem (host-side attribute, capture-safe, idempotent)
    cudaFuncSetAttribute(tgemm_kernel<0>, cudaFuncAttributeMaxDynamicSharedMemorySize, TG_SMEM_BYTES);
    cudaFuncSetAttribute(tgemm_kernel<1>, cudaFuncAttributeMaxDynamicSharedMemorySize, TG_SMEM_BYTES);
    cudaFuncSetAttribute(tgemm_kernel<2>, cudaFuncAttributeMaxDynamicSharedMemorySize, TG_SMEM_BYTES);
    cudaFuncSetAttribute(tgemm_kernel<3>, cudaFuncAttributeMaxDynamicSharedMemorySize, TG_SMEM_BYTES);

    // 1. RMSNorm
    rmsnorm_kernel<<<MROWS, 256>>>(x, pns, xn);

    // 2. h = gelu(xn @ w_mlp_in)   [8192, 4096]
    dim3 g_mlp(MLP_ / 128, MROWS / 128);
    tgemm_kernel<1><<<g_mlp, 256, TG_SMEM_BYTES>>>(xn, w_mlp_in, hbuf,
                                    nullptr, nullptr, nullptr,
                                    MROWS, MLP_, D_);

    // 3. q/k/v = xn @ w{q,k,v}    [8192, 1024] each
    dim3 g_d(D_ / 128, MROWS / 128);
    tgemm_kernel<0><<<g_d, 256, TG_SMEM_BYTES>>>(xn, wq, q, nullptr, nullptr, nullptr,
                                  MROWS, D_, D_);
    tgemm_kernel<0><<<g_d, 256, TG_SMEM_BYTES>>>(xn, wk, k, nullptr, nullptr, nullptr,
                                  MROWS, D_, D_);
    tgemm_kernel<0><<<g_d, 256, TG_SMEM_BYTES>>>(xn, wv, v, nullptr, nullptr, nullptr,
                                  MROWS, D_, D_);

    // 4. attention -> av  [8192, 1024] (cols = h*64+hd)
    dim3 g_attn(S_ / 128, H_, B_);
    attn_kernel<<<g_attn, 128>>>(q, k, v, av);

    // 5. out = residual + h @ w_mlp_out + b_mlp_out + b_attn_out
    tgemm_kernel<2><<<g_d, 256, TG_SMEM_BYTES>>>(hbuf, w_mlp_out, out,
                                  b_mlp_out, b_attn_out, x,
                                  MROWS, D_, MLP_);

    // 6. out += av @ w_attn_out
    tgemm_kernel<3><<<g_d, 256, TG_SMEM_BYTES>>>(av, w_attn_out, out,
                                  nullptr, nullptr, nullptr,
                                  MROWS, D_, D_);
}

// round 8
// speedup vs baseline: 1.7193x; 1.7193x over previous
#include <cuda_runtime.h>
#include <cuda_bf16.h>
#include <cstdint>

#define B_    4
#define S_    2048
#define D_    1024
#define H_    16
#define HD_   64
#define MLP_  4096
#define MROWS (B_*S_)   // 8192

// ---------------------------------------------------------------------------
// Scratch (device globals — no runtime allocation allowed)
// bf16 "planes": hi = bf16(v), lo = bf16(v - hi)
// ---------------------------------------------------------------------------
__device__ __align__(16) uint16_t g_xn_h[(size_t)MROWS * D_];
__device__ __align__(16) uint16_t g_xn_l[(size_t)MROWS * D_];
__device__ __align__(16) uint16_t g_h_h [(size_t)MROWS * MLP_];
__device__ __align__(16) uint16_t g_h_l [(size_t)MROWS * MLP_];
__device__ __align__(16) uint16_t g_av_h[(size_t)MROWS * D_];
__device__ __align__(16) uint16_t g_av_l[(size_t)MROWS * D_];
__device__ float g_q[(size_t)MROWS * D_];
__device__ float g_k[(size_t)MROWS * D_];
__device__ float g_v[(size_t)MROWS * D_];
// weight planes
__device__ __align__(16) uint16_t g_w1_h[(size_t)D_ * MLP_];
__device__ __align__(16) uint16_t g_w1_l[(size_t)D_ * MLP_];
__device__ __align__(16) uint16_t g_wq_h[(size_t)D_ * D_];
__device__ __align__(16) uint16_t g_wq_l[(size_t)D_ * D_];
__device__ __align__(16) uint16_t g_wk_h[(size_t)D_ * D_];
__device__ __align__(16) uint16_t g_wk_l[(size_t)D_ * D_];
__device__ __align__(16) uint16_t g_wv_h[(size_t)D_ * D_];
__device__ __align__(16) uint16_t g_wv_l[(size_t)D_ * D_];
__device__ __align__(16) uint16_t g_w2_h[(size_t)MLP_ * D_];
__device__ __align__(16) uint16_t g_w2_l[(size_t)MLP_ * D_];
__device__ __align__(16) uint16_t g_wo_h[(size_t)D_ * D_];
__device__ __align__(16) uint16_t g_wo_l[(size_t)D_ * D_];

// ---------------------------------------------------------------------------
// Helpers
// ---------------------------------------------------------------------------
__device__ __forceinline__ void bsplit(float v, uint16_t& h, uint16_t& l) {
    __nv_bfloat16 bh = __float2bfloat16(v);
    float r = v - __bfloat162float(bh);
    __nv_bfloat16 bl = __float2bfloat16(r);
    h = __bfloat16_as_ushort(bh);
    l = __bfloat16_as_ushort(bl);
}

__device__ __forceinline__ void ldsm4(uint32_t* d, uint32_t a) {
    asm volatile("ldmatrix.sync.aligned.m8n8.x4.shared.b16 {%0,%1,%2,%3}, [%4];"
                 : "=r"(d[0]), "=r"(d[1]), "=r"(d[2]), "=r"(d[3]) : "r"(a));
}
__device__ __forceinline__ void ldsm4t(uint32_t* d, uint32_t a) {
    asm volatile("ldmatrix.sync.aligned.m8n8.x4.trans.shared.b16 {%0,%1,%2,%3}, [%4];"
                 : "=r"(d[0]), "=r"(d[1]), "=r"(d[2]), "=r"(d[3]) : "r"(a));
}
__device__ __forceinline__ void mma16(float* c, const uint32_t* a, const uint32_t* b) {
    asm volatile(
        "mma.sync.aligned.m16n8k16.row.col.f32.bf16.bf16.f32 "
        "{%0,%1,%2,%3}, {%4,%5,%6,%7}, {%8,%9}, {%0,%1,%2,%3};"
        : "+f"(c[0]), "+f"(c[1]), "+f"(c[2]), "+f"(c[3])
        : "r"(a[0]), "r"(a[1]), "r"(a[2]), "r"(a[3]), "r"(b[0]), "r"(b[1]));
}

// ---------------------------------------------------------------------------
// Elementwise fp32 -> (hi, lo) bf16 plane split (weights)
// ---------------------------------------------------------------------------
__global__ __launch_bounds__(256) void split_kernel(
    const float* __restrict__ src, uint16_t* __restrict__ hi,
    uint16_t* __restrict__ lo, int n)
{
    int i = (blockIdx.x * 256 + threadIdx.x) * 4;
    if (i >= n) return;
    float4 v = *(const float4*)(src + i);
    ushort4 h, l;
    bsplit(v.x, h.x, l.x); bsplit(v.y, h.y, l.y);
    bsplit(v.z, h.z, l.z); bsplit(v.w, h.w, l.w);
    *(ushort4*)(hi + i) = h;
    *(ushort4*)(lo + i) = l;
}

// ---------------------------------------------------------------------------
// RMSNorm: one block per row, emits bf16 hi/lo planes directly
// ---------------------------------------------------------------------------
__global__ __launch_bounds__(256) void rmsnorm_kernel(
    const float* __restrict__ x, const float* __restrict__ scale,
    uint16_t* __restrict__ oh, uint16_t* __restrict__ ol)
{
    int row = blockIdx.x;
    const float4* xr = (const float4*)(x + (size_t)row * D_);
    float4 v = xr[threadIdx.x];
    float s = v.x*v.x + v.y*v.y + v.z*v.z + v.w*v.w;

    __shared__ float red[256];
    red[threadIdx.x] = s;
    __syncthreads();
    #pragma unroll
    for (int off = 128; off > 0; off >>= 1) {
        if (threadIdx.x < off) red[threadIdx.x] += red[threadIdx.x + off];
        __syncthreads();
    }
    float inv = rsqrtf(red[0] * (1.0f / D_) + 1e-6f);

    float4 sc = ((const float4*)scale)[threadIdx.x];
    float o0 = v.x * inv * sc.x, o1 = v.y * inv * sc.y;
    float o2 = v.z * inv * sc.z, o3 = v.w * inv * sc.w;
    ushort4 h, l;
    bsplit(o0, h.x, l.x); bsplit(o1, h.y, l.y);
    bsplit(o2, h.z, l.z); bsplit(o3, h.w, l.w);
    size_t idx = (size_t)row * D_ + threadIdx.x * 4;
    *(ushort4*)(oh + idx) = h;
    *(ushort4*)(ol + idx) = l;
}

// ---------------------------------------------------------------------------
// bf16 split GEMM: C = A @ B with A,B given as bf16 (hi,lo) planes.
// D = Ah*Bh + Ah*Bl + Al*Bh  (~16-bit mantissa accuracy).
// 128x128 tile, BK=16, 256 threads, 8 warps 4(m)x2(n), warp = 32x64.
// Mainloop: LDG.128 -> STS.128 -> ldmatrix -> HMMA only (no cvt).
// A smem [m][k] stride 24 bf16; B smem [k][n] stride 136 bf16 — both
// conflict-free for their ldmatrix patterns.
// EPI: 0 = f32 store, 1 = gelu -> bf16 planes, 2 = +b1+b2+resid f32,
//      3 = += C f32
// ---------------------------------------------------------------------------
template<int EPI>
__global__ __launch_bounds__(256, 2) void bgemm_kernel(
    const uint16_t* __restrict__ Ah, const uint16_t* __restrict__ Al,
    const uint16_t* __restrict__ Bh, const uint16_t* __restrict__ Bl,
    float* __restrict__ C, uint16_t* __restrict__ Chi, uint16_t* __restrict__ Clo,
    const float* __restrict__ bias1, const float* __restrict__ bias2,
    const float* __restrict__ resid,
    int M, int N, int K)
{
    __shared__ __align__(16) uint16_t As[2][2][128][24];   // [stage][plane][m][k]
    __shared__ __align__(16) uint16_t Bs[2][2][16][136];   // [stage][plane][k][n]

    int tid = threadIdx.x;
    int bm = blockIdx.y, bn = blockIdx.x;
    int warp = tid >> 5, lane = tid & 31;
    int wm = (warp & 3) * 32;
    int wn = (warp >> 2) * 64;
    int g = lane >> 2, tg = lane & 3;

    // global load mapping
    int arow = tid >> 1, ak0 = (tid & 1) * 8;      // A: 8 bf16 along k
    int bkr  = tid >> 4, bnc = (tid & 15) * 8;     // B: 8 bf16 along n

    const uint16_t* pAh = Ah + (size_t)(bm * 128 + arow) * K + ak0;
    const uint16_t* pAl = Al + (size_t)(bm * 128 + arow) * K + ak0;
    const uint16_t* pBh = Bh + (size_t)bkr * N + bn * 128 + bnc;
    const uint16_t* pBl = Bl + (size_t)bkr * N + bn * 128 + bnc;

    // ldmatrix lane addressing
    int sub = lane >> 3, r8 = lane & 7;
    int a_lane_off = (((sub & 1) * 8 + r8) * 24 + (sub >> 1) * 8) * 2;
    int b_lane_off = (((sub & 1) * 8 + r8) * 136 + (sub >> 1) * 8) * 2;

    uint32_t sA = (uint32_t)__cvta_generic_to_shared(&As[0][0][0][0]);
    uint32_t sB = (uint32_t)__cvta_generic_to_shared(&Bs[0][0][0][0]);
    // strides (bytes)
    const int A_PL = 128 * 24 * 2;   // 6144
    const int A_ST = 2 * A_PL;       // 12288
    const int B_PL = 16 * 136 * 2;   // 4352
    const int B_ST = 2 * B_PL;       // 8704

    float acc[2][8][4];
    #pragma unroll
    for (int i = 0; i < 2; i++)
        #pragma unroll
        for (int j = 0; j < 8; j++)
            #pragma unroll
            for (int r = 0; r < 4; r++) acc[i][j][r] = 0.0f;

    // prologue: stage 0
    {
        uint4 a_h = *(const uint4*)pAh;
        uint4 a_l = *(const uint4*)pAl;
        uint4 b_h = *(const uint4*)pBh;
        uint4 b_l = *(const uint4*)pBl;
        *(uint4*)&As[0][0][arow][ak0] = a_h;
        *(uint4*)&As[0][1][arow][ak0] = a_l;
        *(uint4*)&Bs[0][0][bkr][bnc]  = b_h;
        *(uint4*)&Bs[0][1][bkr][bnc]  = b_l;
    }
    __syncthreads();

    int s = 0;
    for (int k0 = 0; k0 < K; k0 += 16) {
        uint4 a_h, a_l, b_h, b_l;
        bool pre = (k0 + 16) < K;
        if (pre) {
            a_h = *(const uint4*)(pAh + k0 + 16);
            a_l = *(const uint4*)(pAl + k0 + 16);
            b_h = *(const uint4*)(pBh + (size_t)(k0 + 16) * N);
            b_l = *(const uint4*)(pBl + (size_t)(k0 + 16) * N);
        }

        // A fragments: 2 m-tiles x 2 planes
        uint32_t ah[2][4], al[2][4];
        #pragma unroll
        for (int i = 0; i < 2; i++) {
            int m0 = wm + i * 16;
            ldsm4(ah[i], sA + s * A_ST +         m0 * 48 + a_lane_off);
            ldsm4(al[i], sA + s * A_ST + A_PL +  m0 * 48 + a_lane_off);
        }

        #pragma unroll
        for (int jj = 0; jj < 4; jj++) {
            int n0 = wn + jj * 16;
            uint32_t bh4[4], bl4[4];
            ldsm4t(bh4, sB + s * B_ST +        n0 * 2 + b_lane_off);
            ldsm4t(bl4, sB + s * B_ST + B_PL + n0 * 2 + b_lane_off);
            #pragma unroll
            for (int hf = 0; hf < 2; hf++) {
                int j = jj * 2 + hf;
                uint32_t* bh = bh4 + hf * 2;
                uint32_t* bl = bl4 + hf * 2;
                #pragma unroll
                for (int i = 0; i < 2; i++) {
                    mma16(acc[i][j], ah[i], bh);
                    mma16(acc[i][j], ah[i], bl);
                    mma16(acc[i][j], al[i], bh);
                }
            }
        }

        if (pre) {
            int sn = s ^ 1;
            *(uint4*)&As[sn][0][arow][ak0] = a_h;
            *(uint4*)&As[sn][1][arow][ak0] = a_l;
            *(uint4*)&Bs[sn][0][bkr][bnc]  = b_h;
            *(uint4*)&Bs[sn][1][bkr][bnc]  = b_l;
        }
        __syncthreads();
        s ^= 1;
    }

    // epilogue
    #pragma unroll
    for (int i = 0; i < 2; i++) {
        #pragma unroll
        for (int j = 0; j < 8; j++) {
            int row0 = bm * 128 + wm + i * 16 + g;
            int col  = bn * 128 + wn + j * 8 + tg * 2;
            #pragma unroll
            for (int rr = 0; rr < 2; rr++) {
                int row = row0 + rr * 8;
                size_t idx = (size_t)row * N + col;
                float v0 = acc[i][j][rr * 2 + 0];
                float v1 = acc[i][j][rr * 2 + 1];
                if (EPI == 1) {
                    float t0 = 0.7978845608028654f * (v0 + 0.044715f * v0 * v0 * v0);
                    v0 = 0.5f * v0 * (1.0f + tanhf(t0));
                    float t1 = 0.7978845608028654f * (v1 + 0.044715f * v1 * v1 * v1);
                    v1 = 0.5f * v1 * (1.0f + tanhf(t1));
                    ushort2 h, l;
                    bsplit(v0, h.x, l.x); bsplit(v1, h.y, l.y);
                    *(ushort2*)(Chi + idx) = h;
                    *(ushort2*)(Clo + idx) = l;
                } else {
                    if (EPI == 2) {
                        v0 += bias1[col] + bias2[col] + resid[idx];
                        v1 += bias1[col + 1] + bias2[col + 1] + resid[idx + 1];
                    } else if (EPI == 3) {
                        v0 += C[idx];
                        v1 += C[idx + 1];
                    }
                    C[idx]     = v0;
                    C[idx + 1] = v1;
                }
            }
        }
    }
}

// ---------------------------------------------------------------------------
// Flash attention (fp32 math). Emits av as bf16 hi/lo planes.
// ---------------------------------------------------------------------------
__global__ __launch_bounds__(128) void attn_kernel(
    const float* __restrict__ q, const float* __restrict__ k,
    const float* __restrict__ v,
    uint16_t* __restrict__ avh, uint16_t* __restrict__ avl)
{
    int h = blockIdx.y, b = blockIdx.z;
    int tid = threadIdx.x;
    int qi = blockIdx.x * 128 + tid;

    __shared__ float Ks[32][64];
    __shared__ float Vs[32][64];

    const float* qptr = q + ((size_t)(b * S_ + qi)) * D_ + h * HD_;
    float4 qr[16];
    #pragma unroll
    for (int i = 0; i < 16; i++) qr[i] = ((const float4*)qptr)[i];

    float4 acc[16];
    #pragma unroll
    for (int i = 0; i < 16; i++) acc[i] = make_float4(0.f, 0.f, 0.f, 0.f);

    float m = -1e30f, l = 0.0f;
    const float scale = 0.125f;

    int r = tid >> 2;
    int c = (tid & 3) * 16;

    for (int kt = 0; kt < S_; kt += 32) {
        __syncthreads();
        {
            const float* kp = k + ((size_t)(b * S_ + kt + r)) * D_ + h * HD_ + c;
            const float* vp = v + ((size_t)(b * S_ + kt + r)) * D_ + h * HD_ + c;
            #pragma unroll
            for (int i = 0; i < 4; i++) {
                *(float4*)&Ks[r][c + 4 * i] = ((const float4*)kp)[i];
                *(float4*)&Vs[r][c + 4 * i] = ((const float4*)vp)[i];
            }
        }
        __syncthreads();

        float s[32];
        float tmax = -1e30f;
        #pragma unroll
        for (int j = 0; j < 32; j++) {
            const float4* kr = (const float4*)Ks[j];
            float d0 = 0.f;
            #pragma unroll
            for (int i = 0; i < 16; i++) {
                float4 kk = kr[i];
                d0 = fmaf(qr[i].x, kk.x, d0);
                d0 = fmaf(qr[i].y, kk.y, d0);
                d0 = fmaf(qr[i].z, kk.z, d0);
                d0 = fmaf(qr[i].w, kk.w, d0);
            }
            s[j] = d0 * scale;
            tmax = fmaxf(tmax, s[j]);
        }

        float mnew = fmaxf(m, tmax);
        float corr = __expf(m - mnew);
        l *= corr;
        #pragma unroll
        for (int i = 0; i < 16; i++) {
            acc[i].x *= corr; acc[i].y *= corr;
            acc[i].z *= corr; acc[i].w *= corr;
        }
        m = mnew;

        #pragma unroll
        for (int j = 0; j < 32; j++) {
            float p = __expf(s[j] - m);
            l += p;
            const float4* vr = (const float4*)Vs[j];
            #pragma unroll
            for (int i = 0; i < 16; i++) {
                float4 vv = vr[i];
                acc[i].x = fmaf(p, vv.x, acc[i].x);
                acc[i].y = fmaf(p, vv.y, acc[i].y);
                acc[i].z = fmaf(p, vv.z, acc[i].z);
                acc[i].w = fmaf(p, vv.w, acc[i].w);
            }
        }
    }

    float invl = 1.0f / l;
    size_t obase = ((size_t)(b * S_ + qi)) * D_ + h * HD_;
    #pragma unroll
    for (int i = 0; i < 16; i++) {
        float o0 = acc[i].x * invl, o1 = acc[i].y * invl;
        float o2 = acc[i].z * invl, o3 = acc[i].w * invl;
        ushort4 hh, ll;
        bsplit(o0, hh.x, ll.x); bsplit(o1, hh.y, ll.y);
        bsplit(o2, hh.z, ll.z); bsplit(o3, hh.w, ll.w);
        *(ushort4*)(avh + obase + i * 4) = hh;
        *(ushort4*)(avl + obase + i * 4) = ll;
    }
}

// ---------------------------------------------------------------------------
// Launch
// ---------------------------------------------------------------------------
extern "C" void kernel_launch(void* const* d_in, const int* in_sizes, int n_in,
                              void* d_out, int out_size)
{
    const float* x          = (const float*)d_in[0];
    const float* pns        = (const float*)d_in[1];
    const float* w_mlp_in   = (const float*)d_in[2];
    const float* wq         = (const float*)d_in[3];
    const float* wk         = (const float*)d_in[4];
    const float* wv         = (const float*)d_in[5];
    const float* w_mlp_out  = (const float*)d_in[6];
    const float* b_mlp_out  = (const float*)d_in[7];
    const float* w_attn_out = (const float*)d_in[8];
    const float* b_attn_out = (const float*)d_in[9];
    float* out = (float*)d_out;

    uint16_t *xnh, *xnl, *hh, *hl, *avh, *avl;
    uint16_t *w1h, *w1l, *wqh, *wql, *wkh, *wkl, *wvh, *wvl, *w2h, *w2l, *woh, *wol;
    float *q, *k, *v;
    cudaGetSymbolAddress((void**)&xnh, g_xn_h); cudaGetSymbolAddress((void**)&xnl, g_xn_l);
    cudaGetSymbolAddress((void**)&hh,  g_h_h);  cudaGetSymbolAddress((void**)&hl,  g_h_l);
    cudaGetSymbolAddress((void**)&avh, g_av_h); cudaGetSymbolAddress((void**)&avl, g_av_l);
    cudaGetSymbolAddress((void**)&w1h, g_w1_h); cudaGetSymbolAddress((void**)&w1l, g_w1_l);
    cudaGetSymbolAddress((void**)&wqh, g_wq_h); cudaGetSymbolAddress((void**)&wql, g_wq_l);
    cudaGetSymbolAddress((void**)&wkh, g_wk_h); cudaGetSymbolAddress((void**)&wkl, g_wk_l);
    cudaGetSymbolAddress((void**)&wvh, g_wv_h); cudaGetSymbolAddress((void**)&wvl, g_wv_l);
    cudaGetSymbolAddress((void**)&w2h, g_w2_h); cudaGetSymbolAddress((void**)&w2l, g_w2_l);
    cudaGetSymbolAddress((void**)&woh, g_wo_h); cudaGetSymbolAddress((void**)&wol, g_wo_l);
    cudaGetSymbolAddress((void**)&q, g_q);
    cudaGetSymbolAddress((void**)&k, g_k);
    cudaGetSymbolAddress((void**)&v, g_v);

    // 0. weight splits (cheap, memory-bound)
    const int DM = D_ * MLP_, DD = D_ * D_;
    split_kernel<<<DM / 1024, 256>>>(w_mlp_in,  w1h, w1l, DM);
    split_kernel<<<DD / 1024, 256>>>(wq,        wqh, wql, DD);
    split_kernel<<<DD / 1024, 256>>>(wk,        wkh, wkl, DD);
    split_kernel<<<DD / 1024, 256>>>(wv,        wvh, wvl, DD);
    split_kernel<<<DM / 1024, 256>>>(w_mlp_out, w2h, w2l, DM);
    split_kernel<<<DD / 1024, 256>>>(w_attn_out, woh, wol, DD);

    // 1. RMSNorm -> xn planes
    rmsnorm_kernel<<<MROWS, 256>>>(x, pns, xnh, xnl);

    // 2. h = gelu(xn @ w_mlp_in) -> h planes
    dim3 g_mlp(MLP_ / 128, MROWS / 128);
    bgemm_kernel<1><<<g_mlp, 256>>>(xnh, xnl, w1h, w1l,
                                    nullptr, hh, hl,
                                    nullptr, nullptr, nullptr,
                                    MROWS, MLP_, D_);

    // 3. q/k/v = xn @ w{q,k,v}  (fp32 out for attention)
    dim3 g_d(D_ / 128, MROWS / 128);
    bgemm_kernel<0><<<g_d, 256>>>(xnh, xnl, wqh, wql, q, nullptr, nullptr,
                                  nullptr, nullptr, nullptr, MROWS, D_, D_);
    bgemm_kernel<0><<<g_d, 256>>>(xnh, xnl, wkh, wkl, k, nullptr, nullptr,
                                  nullptr, nullptr, nullptr, MROWS, D_, D_);
    bgemm_kernel<0><<<g_d, 256>>>(xnh, xnl, wvh, wvl, v, nullptr, nullptr,
                                  nullptr, nullptr, nullptr, MROWS, D_, D_);

    // 4. attention -> av planes
    dim3 g_attn(S_ / 128, H_, B_);
    attn_kernel<<<g_attn, 128>>>(q, k, v, avh, avl);

    // 5. out = resid + h @ w_mlp_out + b_mlp_out + b_attn_out
    bgemm_kernel<2><<<g_d, 256>>>(hh, hl, w2h, w2l, out, nullptr, nullptr,
                                  b_mlp_out, b_attn_out, x, MROWS, D_, MLP_);

    // 6. out += av @ w_attn_out
    bgemm_kernel<3><<<g_d, 256>>>(avh, avl, woh, wol, out, nullptr, nullptr,
                                  nullptr, nullptr, nullptr, MROWS, D_, D_);
}

// round 9
// speedup vs baseline: 2.8460x; 1.6554x over previous
#include <cuda_runtime.h>
#include <cuda_bf16.h>
#include <cstdint>

#define B_    4
#define S_    2048
#define D_    1024
#define H_    16
#define HD_   64
#define MLP_  4096
#define MROWS (B_*S_)   // 8192

// ---------------------------------------------------------------------------
// Scratch (device globals). bf16 planes: hi = bf16(v), lo = bf16(v - hi)
// ---------------------------------------------------------------------------
__device__ __align__(16) uint16_t g_xn_h[(size_t)MROWS * D_];
__device__ __align__(16) uint16_t g_xn_l[(size_t)MROWS * D_];
__device__ __align__(16) uint16_t g_h_h [(size_t)MROWS * MLP_];
__device__ __align__(16) uint16_t g_h_l [(size_t)MROWS * MLP_];
__device__ __align__(16) uint16_t g_av_h[(size_t)MROWS * D_];
__device__ __align__(16) uint16_t g_av_l[(size_t)MROWS * D_];
__device__ __align__(16) uint16_t g_q_h [(size_t)MROWS * D_];
__device__ __align__(16) uint16_t g_q_l [(size_t)MROWS * D_];
__device__ __align__(16) uint16_t g_k_h [(size_t)MROWS * D_];
__device__ __align__(16) uint16_t g_k_l [(size_t)MROWS * D_];
__device__ __align__(16) uint16_t g_v_h [(size_t)MROWS * D_];
__device__ __align__(16) uint16_t g_v_l [(size_t)MROWS * D_];
// weight planes
__device__ __align__(16) uint16_t g_w1_h[(size_t)D_ * MLP_];
__device__ __align__(16) uint16_t g_w1_l[(size_t)D_ * MLP_];
__device__ __align__(16) uint16_t g_wq_h[(size_t)D_ * D_];
__device__ __align__(16) uint16_t g_wq_l[(size_t)D_ * D_];
__device__ __align__(16) uint16_t g_wk_h[(size_t)D_ * D_];
__device__ __align__(16) uint16_t g_wk_l[(size_t)D_ * D_];
__device__ __align__(16) uint16_t g_wv_h[(size_t)D_ * D_];
__device__ __align__(16) uint16_t g_wv_l[(size_t)D_ * D_];
__device__ __align__(16) uint16_t g_w2_h[(size_t)MLP_ * D_];
__device__ __align__(16) uint16_t g_w2_l[(size_t)MLP_ * D_];
__device__ __align__(16) uint16_t g_wo_h[(size_t)D_ * D_];
__device__ __align__(16) uint16_t g_wo_l[(size_t)D_ * D_];

// ---------------------------------------------------------------------------
// Helpers
// ---------------------------------------------------------------------------
__device__ __forceinline__ void bsplit(float v, uint16_t& h, uint16_t& l) {
    __nv_bfloat16 bh = __float2bfloat16(v);
    float r = v - __bfloat162float(bh);
    __nv_bfloat16 bl = __float2bfloat16(r);
    h = __bfloat16_as_ushort(bh);
    l = __bfloat16_as_ushort(bl);
}
// pack two floats into bf16x2 hi-plane and lo-plane regs (low half = first)
__device__ __forceinline__ void packsplit(float a, float b, uint32_t& hi, uint32_t& lo) {
    uint16_t ah, al, bh, bl;
    bsplit(a, ah, al);
    bsplit(b, bh, bl);
    hi = (uint32_t)ah | ((uint32_t)bh << 16);
    lo = (uint32_t)al | ((uint32_t)bl << 16);
}

__device__ __forceinline__ void ldsm4(uint32_t* d, uint32_t a) {
    asm volatile("ldmatrix.sync.aligned.m8n8.x4.shared.b16 {%0,%1,%2,%3}, [%4];"
                 : "=r"(d[0]), "=r"(d[1]), "=r"(d[2]), "=r"(d[3]) : "r"(a));
}
__device__ __forceinline__ void ldsm4t(uint32_t* d, uint32_t a) {
    asm volatile("ldmatrix.sync.aligned.m8n8.x4.trans.shared.b16 {%0,%1,%2,%3}, [%4];"
                 : "=r"(d[0]), "=r"(d[1]), "=r"(d[2]), "=r"(d[3]) : "r"(a));
}
__device__ __forceinline__ void mma16(float* c, const uint32_t* a, const uint32_t* b) {
    asm volatile(
        "mma.sync.aligned.m16n8k16.row.col.f32.bf16.bf16.f32 "
        "{%0,%1,%2,%3}, {%4,%5,%6,%7}, {%8,%9}, {%0,%1,%2,%3};"
        : "+f"(c[0]), "+f"(c[1]), "+f"(c[2]), "+f"(c[3])
        : "r"(a[0]), "r"(a[1]), "r"(a[2]), "r"(a[3]), "r"(b[0]), "r"(b[1]));
}
__device__ __forceinline__ void cpa16(uint32_t smem, const void* g) {
    asm volatile("cp.async.cg.shared.global [%0], [%1], 16;" :: "r"(smem), "l"(g));
}
#define CP_COMMIT() asm volatile("cp.async.commit_group;")

// ---------------------------------------------------------------------------
// Elementwise fp32 -> (hi, lo) bf16 plane split (weights)
// ---------------------------------------------------------------------------
__global__ __launch_bounds__(256) void split_kernel(
    const float* __restrict__ src, uint16_t* __restrict__ hi,
    uint16_t* __restrict__ lo, int n)
{
    int i = (blockIdx.x * 256 + threadIdx.x) * 4;
    if (i >= n) return;
    float4 v = *(const float4*)(src + i);
    ushort4 h, l;
    bsplit(v.x, h.x, l.x); bsplit(v.y, h.y, l.y);
    bsplit(v.z, h.z, l.z); bsplit(v.w, h.w, l.w);
    *(ushort4*)(hi + i) = h;
    *(ushort4*)(lo + i) = l;
}

// ---------------------------------------------------------------------------
// RMSNorm -> bf16 hi/lo planes
// ---------------------------------------------------------------------------
__global__ __launch_bounds__(256) void rmsnorm_kernel(
    const float* __restrict__ x, const float* __restrict__ scale,
    uint16_t* __restrict__ oh, uint16_t* __restrict__ ol)
{
    int row = blockIdx.x;
    const float4* xr = (const float4*)(x + (size_t)row * D_);
    float4 v = xr[threadIdx.x];
    float s = v.x*v.x + v.y*v.y + v.z*v.z + v.w*v.w;

    __shared__ float red[256];
    red[threadIdx.x] = s;
    __syncthreads();
    #pragma unroll
    for (int off = 128; off > 0; off >>= 1) {
        if (threadIdx.x < off) red[threadIdx.x] += red[threadIdx.x + off];
        __syncthreads();
    }
    float inv = rsqrtf(red[0] * (1.0f / D_) + 1e-6f);

    float4 sc = ((const float4*)scale)[threadIdx.x];
    float o0 = v.x * inv * sc.x, o1 = v.y * inv * sc.y;
    float o2 = v.z * inv * sc.z, o3 = v.w * inv * sc.w;
    ushort4 h, l;
    bsplit(o0, h.x, l.x); bsplit(o1, h.y, l.y);
    bsplit(o2, h.z, l.z); bsplit(o3, h.w, l.w);
    size_t idx = (size_t)row * D_ + threadIdx.x * 4;
    *(ushort4*)(oh + idx) = h;
    *(ushort4*)(ol + idx) = l;
}

// ---------------------------------------------------------------------------
// bf16 split GEMM (as R8). EPI: 0 f32, 1 gelu->planes, 2 +b1+b2+resid,
// 3 +=C, 4 planes (no gelu)
// ---------------------------------------------------------------------------
template<int EPI>
__global__ __launch_bounds__(256, 2) void bgemm_kernel(
    const uint16_t* __restrict__ Ah, const uint16_t* __restrict__ Al,
    const uint16_t* __restrict__ Bh, const uint16_t* __restrict__ Bl,
    float* __restrict__ C, uint16_t* __restrict__ Chi, uint16_t* __restrict__ Clo,
    const float* __restrict__ bias1, const float* __restrict__ bias2,
    const float* __restrict__ resid,
    int M, int N, int K)
{
    __shared__ __align__(16) uint16_t As[2][2][128][24];
    __shared__ __align__(16) uint16_t Bs[2][2][16][136];

    int tid = threadIdx.x;
    int bm = blockIdx.y, bn = blockIdx.x;
    int warp = tid >> 5, lane = tid & 31;
    int wm = (warp & 3) * 32;
    int wn = (warp >> 2) * 64;
    int g = lane >> 2, tg = lane & 3;

    int arow = tid >> 1, ak0 = (tid & 1) * 8;
    int bkr  = tid >> 4, bnc = (tid & 15) * 8;

    const uint16_t* pAh = Ah + (size_t)(bm * 128 + arow) * K + ak0;
    const uint16_t* pAl = Al + (size_t)(bm * 128 + arow) * K + ak0;
    const uint16_t* pBh = Bh + (size_t)bkr * N + bn * 128 + bnc;
    const uint16_t* pBl = Bl + (size_t)bkr * N + bn * 128 + bnc;

    int sub = lane >> 3, r8 = lane & 7;
    int a_lane_off = (((sub & 1) * 8 + r8) * 24 + (sub >> 1) * 8) * 2;
    int b_lane_off = (((sub & 1) * 8 + r8) * 136 + (sub >> 1) * 8) * 2;

    uint32_t sA = (uint32_t)__cvta_generic_to_shared(&As[0][0][0][0]);
    uint32_t sB = (uint32_t)__cvta_generic_to_shared(&Bs[0][0][0][0]);
    const int A_PL = 128 * 24 * 2;
    const int A_ST = 2 * A_PL;
    const int B_PL = 16 * 136 * 2;
    const int B_ST = 2 * B_PL;

    float acc[2][8][4];
    #pragma unroll
    for (int i = 0; i < 2; i++)
        #pragma unroll
        for (int j = 0; j < 8; j++)
            #pragma unroll
            for (int r = 0; r < 4; r++) acc[i][j][r] = 0.0f;

    {
        uint4 a_h = *(const uint4*)pAh;
        uint4 a_l = *(const uint4*)pAl;
        uint4 b_h = *(const uint4*)pBh;
        uint4 b_l = *(const uint4*)pBl;
        *(uint4*)&As[0][0][arow][ak0] = a_h;
        *(uint4*)&As[0][1][arow][ak0] = a_l;
        *(uint4*)&Bs[0][0][bkr][bnc]  = b_h;
        *(uint4*)&Bs[0][1][bkr][bnc]  = b_l;
    }
    __syncthreads();

    int s = 0;
    for (int k0 = 0; k0 < K; k0 += 16) {
        uint4 a_h, a_l, b_h, b_l;
        bool pre = (k0 + 16) < K;
        if (pre) {
            a_h = *(const uint4*)(pAh + k0 + 16);
            a_l = *(const uint4*)(pAl + k0 + 16);
            b_h = *(const uint4*)(pBh + (size_t)(k0 + 16) * N);
            b_l = *(const uint4*)(pBl + (size_t)(k0 + 16) * N);
        }

        uint32_t ah[2][4], al[2][4];
        #pragma unroll
        for (int i = 0; i < 2; i++) {
            int m0 = wm + i * 16;
            ldsm4(ah[i], sA + s * A_ST +        m0 * 48 + a_lane_off);
            ldsm4(al[i], sA + s * A_ST + A_PL + m0 * 48 + a_lane_off);
        }

        #pragma unroll
        for (int jj = 0; jj < 4; jj++) {
            int n0 = wn + jj * 16;
            uint32_t bh4[4], bl4[4];
            ldsm4t(bh4, sB + s * B_ST +        n0 * 2 + b_lane_off);
            ldsm4t(bl4, sB + s * B_ST + B_PL + n0 * 2 + b_lane_off);
            #pragma unroll
            for (int hf = 0; hf < 2; hf++) {
                int j = jj * 2 + hf;
                uint32_t* bh = bh4 + hf * 2;
                uint32_t* bl = bl4 + hf * 2;
                #pragma unroll
                for (int i = 0; i < 2; i++) {
                    mma16(acc[i][j], ah[i], bh);
                    mma16(acc[i][j], ah[i], bl);
                    mma16(acc[i][j], al[i], bh);
                }
            }
        }

        if (pre) {
            int sn = s ^ 1;
            *(uint4*)&As[sn][0][arow][ak0] = a_h;
            *(uint4*)&As[sn][1][arow][ak0] = a_l;
            *(uint4*)&Bs[sn][0][bkr][bnc]  = b_h;
            *(uint4*)&Bs[sn][1][bkr][bnc]  = b_l;
        }
        __syncthreads();
        s ^= 1;
    }

    #pragma unroll
    for (int i = 0; i < 2; i++) {
        #pragma unroll
        for (int j = 0; j < 8; j++) {
            int row0 = bm * 128 + wm + i * 16 + g;
            int col  = bn * 128 + wn + j * 8 + tg * 2;
            #pragma unroll
            for (int rr = 0; rr < 2; rr++) {
                int row = row0 + rr * 8;
                size_t idx = (size_t)row * N + col;
                float v0 = acc[i][j][rr * 2 + 0];
                float v1 = acc[i][j][rr * 2 + 1];
                if (EPI == 1 || EPI == 4) {
                    if (EPI == 1) {
                        float t0 = 0.7978845608028654f * (v0 + 0.044715f * v0 * v0 * v0);
                        v0 = 0.5f * v0 * (1.0f + tanhf(t0));
                        float t1 = 0.7978845608028654f * (v1 + 0.044715f * v1 * v1 * v1);
                        v1 = 0.5f * v1 * (1.0f + tanhf(t1));
                    }
                    ushort2 h, l;
                    bsplit(v0, h.x, l.x); bsplit(v1, h.y, l.y);
                    *(ushort2*)(Chi + idx) = h;
                    *(ushort2*)(Clo + idx) = l;
                } else {
                    if (EPI == 2) {
                        v0 += bias1[col] + bias2[col] + resid[idx];
                        v1 += bias1[col + 1] + bias2[col + 1] + resid[idx + 1];
                    } else if (EPI == 3) {
                        v0 += C[idx];
                        v1 += C[idx + 1];
                    }
                    C[idx]     = v0;
                    C[idx + 1] = v1;
                }
            }
        }
    }
}

// ---------------------------------------------------------------------------
// Tensor-core flash attention, bf16 3-plane splits throughout.
// Grid (S/128, H, B), 256 threads = 8 warps, each warp 16 query rows.
// K/V tiles of 64 keys double-buffered in smem via cp.async.
// smem row stride = 72 bf16 (144B) -> conflict-free ldmatrix.
// ---------------------------------------------------------------------------
#define AT_BUF   9216u           // one 64x72 bf16 plane, bytes
#define AT_STAGE (4u * AT_BUF)   // Kh,Kl,Vh,Vl
#define AT_SMEM  (2u * AT_STAGE) // 73728 bytes

__global__ __launch_bounds__(256) void fattn_kernel(
    const uint16_t* __restrict__ qh, const uint16_t* __restrict__ ql,
    const uint16_t* __restrict__ kh, const uint16_t* __restrict__ kl,
    const uint16_t* __restrict__ vh, const uint16_t* __restrict__ vl,
    uint16_t* __restrict__ avh, uint16_t* __restrict__ avl)
{
    extern __shared__ __align__(16) uint16_t sm[];
    int h = blockIdx.y, b = blockIdx.z;
    int tid = threadIdx.x, warp = tid >> 5, lane = tid & 31;
    int g = lane >> 2, tg = lane & 3, r8 = lane & 7;
    uint32_t smb = (uint32_t)__cvta_generic_to_shared(sm);

    // ---- stage Q (aliases stage area), ldmatrix fragments ----
    {
        int row = tid >> 1;
        int half = (tid & 1) * 32;
        size_t gq = ((size_t)b * S_ + blockIdx.x * 128 + row) * D_ + h * HD_ + half;
        #pragma unroll
        for (int i = 0; i < 4; i++) {
            *(uint4*)(sm + row * 72 + half + i * 8)        = *(const uint4*)(qh + gq + i * 8);
            *(uint4*)(sm + 9216 + row * 72 + half + i * 8) = *(const uint4*)(ql + gq + i * 8);
        }
    }
    __syncthreads();
    uint32_t qfh[4][4], qfl[4][4];
    {
        int qr = warp * 16 + r8 + ((lane >> 3) & 1) * 8;
        #pragma unroll
        for (int ks = 0; ks < 4; ks++) {
            int col = ks * 16 + ((lane >> 4) & 1) * 8;
            ldsm4(qfh[ks], smb +         (qr * 72 + col) * 2);
            ldsm4(qfl[ks], smb + 18432 + (qr * 72 + col) * 2);
        }
    }
    __syncthreads();

    // cp.async loader: thread covers one row of one buffer
    int buf = tid >> 6;       // 0 Kh, 1 Kl, 2 Vh, 3 Vl
    int u   = tid & 63;       // key row within tile
    const uint16_t* gsrc;
    {
        const uint16_t* bases[4] = { kh, kl, vh, vl };
        gsrc = bases[buf] + ((size_t)b * S_ + u) * D_ + h * HD_;
    }
    uint32_t sdst = smb + buf * AT_BUF + u * 144;

    float o[8][4];
    #pragma unroll
    for (int j = 0; j < 8; j++)
        #pragma unroll
        for (int r = 0; r < 4; r++) o[j][r] = 0.0f;
    float m0 = -1e30f, m1 = -1e30f, l0 = 0.0f, l1 = 0.0f;

    // prologue: stage 0, tile 0
    {
        const uint16_t* src = gsrc;
        #pragma unroll
        for (int i = 0; i < 8; i++) cpa16(sdst + i * 16, src + i * 8);
        CP_COMMIT();
    }

    for (int it = 0; it < S_ / 64; it++) {
        if (it + 1 < S_ / 64) {
            const uint16_t* src = gsrc + (size_t)(it + 1) * 64 * D_;
            uint32_t dst = sdst + ((it + 1) & 1) * AT_STAGE;
            #pragma unroll
            for (int i = 0; i < 8; i++) cpa16(dst + i * 16, src + i * 8);
            CP_COMMIT();
            asm volatile("cp.async.wait_group 1;");
        } else {
            asm volatile("cp.async.wait_group 0;");
        }
        __syncthreads();

        uint32_t kb = smb + (it & 1) * AT_STAGE;
        uint32_t vb = kb + 2 * AT_BUF;

        // ---- S = Q @ K^T (3-plane) ----
        float sc[8][4];
        #pragma unroll
        for (int j = 0; j < 8; j++)
            #pragma unroll
            for (int r = 0; r < 4; r++) sc[j][r] = 0.0f;

        #pragma unroll
        for (int ks = 0; ks < 4; ks++) {
            #pragma unroll
            for (int j2 = 0; j2 < 4; j2++) {
                int key = j2 * 16 + r8 + ((lane >> 4) & 1) * 8;
                int col = ks * 16 + ((lane >> 3) & 1) * 8;
                uint32_t off = key * 144 + col * 2;
                uint32_t bh4[4], bl4[4];
                ldsm4(bh4, kb + off);
                ldsm4(bl4, kb + AT_BUF + off);
                mma16(sc[2*j2],   qfh[ks], &bh4[0]);
                mma16(sc[2*j2],   qfl[ks], &bh4[0]);
                mma16(sc[2*j2],   qfh[ks], &bl4[0]);
                mma16(sc[2*j2+1], qfh[ks], &bh4[2]);
                mma16(sc[2*j2+1], qfl[ks], &bh4[2]);
                mma16(sc[2*j2+1], qfh[ks], &bl4[2]);
            }
        }

        // ---- online softmax ----
        const float scale = 0.125f;
        float mx0 = -1e30f, mx1 = -1e30f;
        #pragma unroll
        for (int j = 0; j < 8; j++) {
            sc[j][0] *= scale; sc[j][1] *= scale;
            sc[j][2] *= scale; sc[j][3] *= scale;
            mx0 = fmaxf(mx0, fmaxf(sc[j][0], sc[j][1]));
            mx1 = fmaxf(mx1, fmaxf(sc[j][2], sc[j][3]));
        }
        mx0 = fmaxf(mx0, __shfl_xor_sync(0xffffffffu, mx0, 1));
        mx0 = fmaxf(mx0, __shfl_xor_sync(0xffffffffu, mx0, 2));
        mx1 = fmaxf(mx1, __shfl_xor_sync(0xffffffffu, mx1, 1));
        mx1 = fmaxf(mx1, __shfl_xor_sync(0xffffffffu, mx1, 2));
        float nm0 = fmaxf(m0, mx0), nm1 = fmaxf(m1, mx1);
        float c0 = __expf(m0 - nm0), c1 = __expf(m1 - nm1);
        m0 = nm0; m1 = nm1;
        l0 *= c0; l1 *= c1;
        #pragma unroll
        for (int j = 0; j < 8; j++) {
            o[j][0] *= c0; o[j][1] *= c0;
            o[j][2] *= c1; o[j][3] *= c1;
        }
        #pragma unroll
        for (int j = 0; j < 8; j++) {
            float p0 = __expf(sc[j][0] - m0); sc[j][0] = p0; l0 += p0;
            float p1 = __expf(sc[j][1] - m0); sc[j][1] = p1; l0 += p1;
            float p2 = __expf(sc[j][2] - m1); sc[j][2] = p2; l1 += p2;
            float p3 = __expf(sc[j][3] - m1); sc[j][3] = p3; l1 += p3;
        }

        // ---- O += P @ V (3-plane) ----
        #pragma unroll
        for (int kt = 0; kt < 4; kt++) {
            int ja = 2 * kt, jb = 2 * kt + 1;
            uint32_t pah[4], pal[4];
            packsplit(sc[ja][0], sc[ja][1], pah[0], pal[0]);
            packsplit(sc[ja][2], sc[ja][3], pah[1], pal[1]);
            packsplit(sc[jb][0], sc[jb][1], pah[2], pal[2]);
            packsplit(sc[jb][2], sc[jb][3], pah[3], pal[3]);
            #pragma unroll
            for (int jn2 = 0; jn2 < 4; jn2++) {
                int key = kt * 16 + r8 + ((lane >> 3) & 1) * 8;
                int col = jn2 * 16 + ((lane >> 4) & 1) * 8;
                uint32_t off = key * 144 + col * 2;
                uint32_t dh[4], dl[4];
                ldsm4t(dh, vb + off);
                ldsm4t(dl, vb + AT_BUF + off);
                mma16(o[2*jn2],   pah, &dh[0]);
                mma16(o[2*jn2],   pal, &dh[0]);
                mma16(o[2*jn2],   pah, &dl[0]);
                mma16(o[2*jn2+1], pah, &dh[2]);
                mma16(o[2*jn2+1], pal, &dh[2]);
                mma16(o[2*jn2+1], pah, &dl[2]);
            }
        }
        __syncthreads();
    }

    // ---- finalize: full row sums, normalize, write av planes ----
    l0 += __shfl_xor_sync(0xffffffffu, l0, 1);
    l0 += __shfl_xor_sync(0xffffffffu, l0, 2);
    l1 += __shfl_xor_sync(0xffffffffu, l1, 1);
    l1 += __shfl_xor_sync(0xffffffffu, l1, 2);
    float inv0 = 1.0f / l0, inv1 = 1.0f / l1;

    int row0 = blockIdx.x * 128 + warp * 16 + g;
    size_t base0 = ((size_t)b * S_ + row0) * D_ + h * HD_;
    size_t base1 = base0 + (size_t)8 * D_;
    #pragma unroll
    for (int j = 0; j < 8; j++) {
        int col = j * 8 + tg * 2;
        ushort2 hh, ll;
        bsplit(o[j][0] * inv0, hh.x, ll.x);
        bsplit(o[j][1] * inv0, hh.y, ll.y);
        *(ushort2*)(avh + base0 + col) = hh;
        *(ushort2*)(avl + base0 + col) = ll;
        bsplit(o[j][2] * inv1, hh.x, ll.x);
        bsplit(o[j][3] * inv1, hh.y, ll.y);
        *(ushort2*)(avh + base1 + col) = hh;
        *(ushort2*)(avl + base1 + col) = ll;
    }
}

// ---------------------------------------------------------------------------
// Launch
// ---------------------------------------------------------------------------
extern "C" void kernel_launch(void* const* d_in, const int* in_sizes, int n_in,
                              void* d_out, int out_size)
{
    const float* x          = (const float*)d_in[0];
    const float* pns        = (const float*)d_in[1];
    const float* w_mlp_in   = (const float*)d_in[2];
    const float* wq         = (const float*)d_in[3];
    const float* wk         = (const float*)d_in[4];
    const float* wv         = (const float*)d_in[5];
    const float* w_mlp_out  = (const float*)d_in[6];
    const float* b_mlp_out  = (const float*)d_in[7];
    const float* w_attn_out = (const float*)d_in[8];
    const float* b_attn_out = (const float*)d_in[9];
    float* out = (float*)d_out;

    uint16_t *xnh, *xnl, *hh, *hl, *avh, *avl;
    uint16_t *qhp, *qlp, *khp, *klp, *vhp, *vlp;
    uint16_t *w1h, *w1l, *wqh, *wql, *wkh, *wkl, *wvh, *wvl, *w2h, *w2l, *woh, *wol;
    cudaGetSymbolAddress((void**)&xnh, g_xn_h); cudaGetSymbolAddress((void**)&xnl, g_xn_l);
    cudaGetSymbolAddress((void**)&hh,  g_h_h);  cudaGetSymbolAddress((void**)&hl,  g_h_l);
    cudaGetSymbolAddress((void**)&avh, g_av_h); cudaGetSymbolAddress((void**)&avl, g_av_l);
    cudaGetSymbolAddress((void**)&qhp, g_q_h);  cudaGetSymbolAddress((void**)&qlp, g_q_l);
    cudaGetSymbolAddress((void**)&khp, g_k_h);  cudaGetSymbolAddress((void**)&klp, g_k_l);
    cudaGetSymbolAddress((void**)&vhp, g_v_h);  cudaGetSymbolAddress((void**)&vlp, g_v_l);
    cudaGetSymbolAddress((void**)&w1h, g_w1_h); cudaGetSymbolAddress((void**)&w1l, g_w1_l);
    cudaGetSymbolAddress((void**)&wqh, g_wq_h); cudaGetSymbolAddress((void**)&wql, g_wq_l);
    cudaGetSymbolAddress((void**)&wkh, g_wk_h); cudaGetSymbolAddress((void**)&wkl, g_wk_l);
    cudaGetSymbolAddress((void**)&wvh, g_wv_h); cudaGetSymbolAddress((void**)&wvl, g_wv_l);
    cudaGetSymbolAddress((void**)&w2h, g_w2_h); cudaGetSymbolAddress((void**)&w2l, g_w2_l);
    cudaGetSymbolAddress((void**)&woh, g_wo_h); cudaGetSymbolAddress((void**)&wol, g_wo_l);

    cudaFuncSetAttribute(fattn_kernel, cudaFuncAttributeMaxDynamicSharedMemorySize, AT_SMEM);

    // 0. weight splits
    const int DM = D_ * MLP_, DD = D_ * D_;
    split_kernel<<<DM / 1024, 256>>>(w_mlp_in,   w1h, w1l, DM);
    split_kernel<<<DD / 1024, 256>>>(wq,         wqh, wql, DD);
    split_kernel<<<DD / 1024, 256>>>(wk,         wkh, wkl, DD);
    split_kernel<<<DD / 1024, 256>>>(wv,         wvh, wvl, DD);
    split_kernel<<<DM / 1024, 256>>>(w_mlp_out,  w2h, w2l, DM);
    split_kernel<<<DD / 1024, 256>>>(w_attn_out, woh, wol, DD);

    // 1. RMSNorm -> xn planes
    rmsnorm_kernel<<<MROWS, 256>>>(x, pns, xnh, xnl);

    // 2. h = gelu(xn @ w_mlp_in) -> h planes
    dim3 g_mlp(MLP_ / 128, MROWS / 128);
    bgemm_kernel<1><<<g_mlp, 256>>>(xnh, xnl, w1h, w1l,
                                    nullptr, hh, hl,
                                    nullptr, nullptr, nullptr,
                                    MROWS, MLP_, D_);

    // 3. q/k/v = xn @ w{q,k,v} -> bf16 planes
    dim3 g_d(D_ / 128, MROWS / 128);
    bgemm_kernel<4><<<g_d, 256>>>(xnh, xnl, wqh, wql, nullptr, qhp, qlp,
                                  nullptr, nullptr, nullptr, MROWS, D_, D_);
    bgemm_kernel<4><<<g_d, 256>>>(xnh, xnl, wkh, wkl, nullptr, khp, klp,
                                  nullptr, nullptr, nullptr, MROWS, D_, D_);
    bgemm_kernel<4><<<g_d, 256>>>(xnh, xnl, wvh, wvl, nullptr, vhp, vlp,
                                  nullptr, nullptr, nullptr, MROWS, D_, D_);

    // 4. tensor-core flash attention -> av planes
    dim3 g_attn(S_ / 128, H_, B_);
    fattn_kernel<<<g_attn, 256, AT_SMEM>>>(qhp, qlp, khp, klp, vhp, vlp, avh, avl);

    // 5. out = resid + h @ w_mlp_out + b_mlp_out + b_attn_out
    bgemm_kernel<2><<<g_d, 256>>>(hh, hl, w2h, w2l, out, nullptr, nullptr,
                                  b_mlp_out, b_attn_out, x, MROWS, D_, MLP_);

    // 6. out += av @ w_attn_out
    bgemm_kernel<3><<<g_d, 256>>>(avh, avl, woh, wol, out, nullptr, nullptr,
                                  nullptr, nullptr, nullptr, MROWS, D_, D_);
}

// round 14
// speedup vs baseline: 6.5348x; 2.2961x over previous
#include <cuda_runtime.h>
#include <cuda_fp16.h>
#include <cstdint>

#define B_    4
#define S_    2048
#define D_    1024
#define H_    16
#define HD_   64
#define MLP_  4096
#define MROWS (B_*S_)   // 8192

// ---------------------------------------------------------------------------
// Scratch (device globals) — single-plane fp16 activations & weights.
// ---------------------------------------------------------------------------
__device__ __align__(16) uint16_t g_xn[(size_t)MROWS * D_];
__device__ __align__(16) uint16_t g_h [(size_t)MROWS * MLP_];
__device__ __align__(16) uint16_t g_av[(size_t)MROWS * D_];
__device__ __align__(16) uint16_t g_q [(size_t)MROWS * D_];
__device__ __align__(16) uint16_t g_k [(size_t)MROWS * D_];
__device__ __align__(16) uint16_t g_v [(size_t)MROWS * D_];
__device__ __align__(16) uint16_t g_w1[(size_t)D_ * MLP_];
__device__ __align__(16) uint16_t g_wq[(size_t)D_ * D_];
__device__ __align__(16) uint16_t g_wk[(size_t)D_ * D_];
__device__ __align__(16) uint16_t g_wv[(size_t)D_ * D_];
__device__ __align__(16) uint16_t g_w2[(size_t)MLP_ * D_];
__device__ __align__(16) uint16_t g_wo[(size_t)D_ * D_];

// ---------------------------------------------------------------------------
// Scalar helpers
// ---------------------------------------------------------------------------
__device__ __forceinline__ uint16_t f2h(float v) {
    return __half_as_ushort(__float2half_rn(v));
}
__device__ __forceinline__ uint32_t pack2h(float a, float b) {
    return (uint32_t)f2h(a) | ((uint32_t)f2h(b) << 16);
}
__device__ __forceinline__ float gelu_tanh(float v) {
    float t = 0.7978845608028654f * (v + 0.044715f * v * v * v);
    return 0.5f * v * (1.0f + tanhf(t));
}

// ---------------------------------------------------------------------------
// PTX helpers
// ---------------------------------------------------------------------------
__device__ __forceinline__ void ldsm4(uint32_t* d, uint32_t a) {
    asm volatile("ldmatrix.sync.aligned.m8n8.x4.shared.b16 {%0,%1,%2,%3}, [%4];"
                 : "=r"(d[0]), "=r"(d[1]), "=r"(d[2]), "=r"(d[3]) : "r"(a));
}
__device__ __forceinline__ void ldsm4t(uint32_t* d, uint32_t a) {
    asm volatile("ldmatrix.sync.aligned.m8n8.x4.trans.shared.b16 {%0,%1,%2,%3}, [%4];"
                 : "=r"(d[0]), "=r"(d[1]), "=r"(d[2]), "=r"(d[3]) : "r"(a));
}
__device__ __forceinline__ void mma16(float* c, const uint32_t* a, const uint32_t* b) {
    asm volatile(
        "mma.sync.aligned.m16n8k16.row.col.f32.f16.f16.f32 "
        "{%0,%1,%2,%3}, {%4,%5,%6,%7}, {%8,%9}, {%0,%1,%2,%3};"
        : "+f"(c[0]), "+f"(c[1]), "+f"(c[2]), "+f"(c[3])
        : "r"(a[0]), "r"(a[1]), "r"(a[2]), "r"(a[3]), "r"(b[0]), "r"(b[1]));
}
__device__ __forceinline__ void cpa16(uint32_t smem, const void* g) {
    asm volatile("cp.async.cg.shared.global [%0], [%1], 16;" :: "r"(smem), "l"(g));
}
#define CP_COMMIT() asm volatile("cp.async.commit_group;")

// ---------------------------------------------------------------------------
// fp32 -> fp16 convert (weights)
// ---------------------------------------------------------------------------
__global__ __launch_bounds__(256) void cvt_kernel(
    const float* __restrict__ src, uint16_t* __restrict__ dst, int n)
{
    int i = (blockIdx.x * 256 + threadIdx.x) * 4;
    if (i >= n) return;
    float4 v = *(const float4*)(src + i);
    ushort4 o;
    o.x = f2h(v.x); o.y = f2h(v.y); o.z = f2h(v.z); o.w = f2h(v.w);
    *(ushort4*)(dst + i) = o;
}

// ---------------------------------------------------------------------------
// RMSNorm -> fp16
// ---------------------------------------------------------------------------
__global__ __launch_bounds__(256) void rmsnorm_kernel(
    const float* __restrict__ x, const float* __restrict__ scale,
    uint16_t* __restrict__ o)
{
    int row = blockIdx.x;
    const float4* xr = (const float4*)(x + (size_t)row * D_);
    float4 v = xr[threadIdx.x];
    float s = v.x*v.x + v.y*v.y + v.z*v.z + v.w*v.w;

    __shared__ float red[256];
    red[threadIdx.x] = s;
    __syncthreads();
    #pragma unroll
    for (int off = 128; off > 0; off >>= 1) {
        if (threadIdx.x < off) red[threadIdx.x] += red[threadIdx.x + off];
        __syncthreads();
    }
    float inv = rsqrtf(red[0] * (1.0f / D_) + 1e-6f);

    float4 sc = ((const float4*)scale)[threadIdx.x];
    ushort4 out;
    out.x = f2h(v.x * inv * sc.x);
    out.y = f2h(v.y * inv * sc.y);
    out.z = f2h(v.z * inv * sc.z);
    out.w = f2h(v.w * inv * sc.w);
    *(ushort4*)(o + (size_t)row * D_ + threadIdx.x * 4) = out;
}

// ---------------------------------------------------------------------------
// fp16 GEMM (mma.sync m16n8k16, fp32 accum). 128x128 tile, BK=16, 256 thr,
// 8 warps 4(m)x2(n), warp = 32x64. A smem [m][k] stride 24; B smem [k][n]
// stride 136 — both ldmatrix conflict-free (as R9).
// EPI: 1 gelu->fp16, 2 +b1+b2+resid f32, 3 +=C f32, 4 fp16
// ---------------------------------------------------------------------------
template<int EPI>
__global__ __launch_bounds__(256, 2) void hgemm_kernel(
    const uint16_t* __restrict__ A, const uint16_t* __restrict__ Bm,
    float* __restrict__ C, uint16_t* __restrict__ Ch,
    const float* __restrict__ bias1, const float* __restrict__ bias2,
    const float* __restrict__ resid,
    int M, int N, int K)
{
    __shared__ __align__(16) uint16_t As[2][128][24];
    __shared__ __align__(16) uint16_t Bs[2][16][136];

    int tid = threadIdx.x;
    int bm = blockIdx.y, bn = blockIdx.x;
    int warp = tid >> 5, lane = tid & 31;
    int wm = (warp & 3) * 32;
    int wn = (warp >> 2) * 64;
    int g = lane >> 2, tg = lane & 3;

    int arow = tid >> 1, ak0 = (tid & 1) * 8;
    int bkr  = tid >> 4, bnc = (tid & 15) * 8;

    const uint16_t* pA = A  + (size_t)(bm * 128 + arow) * K + ak0;
    const uint16_t* pB = Bm + (size_t)bkr * N + bn * 128 + bnc;

    int sub = lane >> 3, r8 = lane & 7;
    int a_lane_off = (((sub & 1) * 8 + r8) * 24 + (sub >> 1) * 8) * 2;
    int b_lane_off = (((sub & 1) * 8 + r8) * 136 + (sub >> 1) * 8) * 2;

    uint32_t sA = (uint32_t)__cvta_generic_to_shared(&As[0][0][0]);
    uint32_t sB = (uint32_t)__cvta_generic_to_shared(&Bs[0][0][0]);
    const int A_ST = 128 * 24 * 2;   // bytes per A stage
    const int B_ST = 16 * 136 * 2;   // bytes per B stage

    float acc[2][8][4];
    #pragma unroll
    for (int i = 0; i < 2; i++)
        #pragma unroll
        for (int j = 0; j < 8; j++)
            #pragma unroll
            for (int r = 0; r < 4; r++) acc[i][j][r] = 0.0f;

    {
        uint4 a = *(const uint4*)pA;
        uint4 b = *(const uint4*)pB;
        *(uint4*)&As[0][arow][ak0] = a;
        *(uint4*)&Bs[0][bkr][bnc]  = b;
    }
    __syncthreads();

    int s = 0;
    for (int k0 = 0; k0 < K; k0 += 16) {
        uint4 a, b;
        bool pre = (k0 + 16) < K;
        if (pre) {
            a = *(const uint4*)(pA + k0 + 16);
            b = *(const uint4*)(pB + (size_t)(k0 + 16) * N);
        }

        uint32_t af[2][4];
        #pragma unroll
        for (int i = 0; i < 2; i++) {
            int m0 = wm + i * 16;
            ldsm4(af[i], sA + s * A_ST + m0 * 48 + a_lane_off);
        }

        #pragma unroll
        for (int jj = 0; jj < 4; jj++) {
            int n0 = wn + jj * 16;
            uint32_t bf4[4];
            ldsm4t(bf4, sB + s * B_ST + n0 * 2 + b_lane_off);
            #pragma unroll
            for (int hf = 0; hf < 2; hf++) {
                int j = jj * 2 + hf;
                #pragma unroll
                for (int i = 0; i < 2; i++)
                    mma16(acc[i][j], af[i], bf4 + hf * 2);
            }
        }

        if (pre) {
            int sn = s ^ 1;
            *(uint4*)&As[sn][arow][ak0] = a;
            *(uint4*)&Bs[sn][bkr][bnc]  = b;
        }
        __syncthreads();
        s ^= 1;
    }

    #pragma unroll
    for (int i = 0; i < 2; i++) {
        #pragma unroll
        for (int j = 0; j < 8; j++) {
            int row0 = bm * 128 + wm + i * 16 + g;
            int col  = bn * 128 + wn + j * 8 + tg * 2;
            #pragma unroll
            for (int rr = 0; rr < 2; rr++) {
                int row = row0 + rr * 8;
                size_t idx = (size_t)row * N + col;
                float v0 = acc[i][j][rr * 2 + 0];
                float v1 = acc[i][j][rr * 2 + 1];
                if (EPI == 1 || EPI == 4) {
                    if (EPI == 1) { v0 = gelu_tanh(v0); v1 = gelu_tanh(v1); }
                    ushort2 o;
                    o.x = f2h(v0); o.y = f2h(v1);
                    *(ushort2*)(Ch + idx) = o;
                } else {
                    if (EPI == 2) {
                        v0 += bias1[col] + bias2[col] + resid[idx];
                        v1 += bias1[col + 1] + bias2[col + 1] + resid[idx + 1];
                    } else if (EPI == 3) {
                        v0 += C[idx];
                        v1 += C[idx + 1];
                    }
                    C[idx]     = v0;
                    C[idx + 1] = v1;
                }
            }
        }
    }
}

// ---------------------------------------------------------------------------
// fp16 tensor-core flash attention. Grid (S/128, H, B), 256 thr = 8 warps,
// each warp 16 query rows. K/V tiles (64 keys) double-buffered via cp.async.
// smem row stride = 72 fp16 (144B) — conflict-free ldmatrix (as R9).
// ---------------------------------------------------------------------------
#define AT_BUF   9216u           // one 64x72 fp16 buffer, bytes
#define AT_STAGE (2u * AT_BUF)   // K, V
#define AT_SMEM  (2u * AT_STAGE) // 36864 bytes

__global__ __launch_bounds__(256) void fattn_kernel(
    const uint16_t* __restrict__ qp, const uint16_t* __restrict__ kp,
    const uint16_t* __restrict__ vp, uint16_t* __restrict__ avp)
{
    extern __shared__ __align__(16) uint16_t sm[];
    int h = blockIdx.y, b = blockIdx.z;
    int tid = threadIdx.x, warp = tid >> 5, lane = tid & 31;
    int g = lane >> 2, tg = lane & 3, r8 = lane & 7;
    uint32_t smb = (uint32_t)__cvta_generic_to_shared(sm);

    // ---- stage Q (aliases stage area), load ldmatrix fragments ----
    {
        int row = tid >> 1;
        int half = (tid & 1) * 32;
        size_t gq = ((size_t)b * S_ + blockIdx.x * 128 + row) * D_ + h * HD_ + half;
        #pragma unroll
        for (int i = 0; i < 4; i++)
            *(uint4*)(sm + row * 72 + half + i * 8) = *(const uint4*)(qp + gq + i * 8);
    }
    __syncthreads();
    uint32_t qf[4][4];
    {
        int qr = warp * 16 + r8 + ((lane >> 3) & 1) * 8;
        #pragma unroll
        for (int ks = 0; ks < 4; ks++) {
            int col = ks * 16 + ((lane >> 4) & 1) * 8;
            ldsm4(qf[ks], smb + (qr * 72 + col) * 2);
        }
    }
    __syncthreads();

    // cp.async loader: 2 threads per row, buf 0 = K, buf 1 = V
    int buf = tid >> 7;                // 0..1
    int u   = (tid & 127) >> 1;        // key row 0..63
    int hc  = (tid & 1) * 64;          // byte offset within 128B row data
    const uint16_t* gsrc = (buf ? vp : kp) +
        ((size_t)b * S_ + u) * D_ + h * HD_ + (tid & 1) * 32;
    uint32_t sdst = smb + buf * AT_BUF + u * 144 + hc;

    float o[8][4];
    #pragma unroll
    for (int j = 0; j < 8; j++)
        #pragma unroll
        for (int r = 0; r < 4; r++) o[j][r] = 0.0f;
    float m0 = -1e30f, m1 = -1e30f, l0 = 0.0f, l1 = 0.0f;

    // prologue: stage 0, tile 0
    {
        #pragma unroll
        for (int i = 0; i < 4; i++) cpa16(sdst + i * 16, gsrc + i * 8);
        CP_COMMIT();
    }

    for (int it = 0; it < S_ / 64; it++) {
        if (it + 1 < S_ / 64) {
            const uint16_t* src = gsrc + (size_t)(it + 1) * 64 * D_;
            uint32_t dst = sdst + ((it + 1) & 1) * AT_STAGE;
            #pragma unroll
            for (int i = 0; i < 4; i++) cpa16(dst + i * 16, src + i * 8);
            CP_COMMIT();
            asm volatile("cp.async.wait_group 1;");
        } else {
            asm volatile("cp.async.wait_group 0;");
        }
        __syncthreads();

        uint32_t kb = smb + (it & 1) * AT_STAGE;
        uint32_t vb = kb + AT_BUF;

        // ---- S = Q @ K^T ----
        float sc[8][4];
        #pragma unroll
        for (int j = 0; j < 8; j++)
            #pragma unroll
            for (int r = 0; r < 4; r++) sc[j][r] = 0.0f;

        #pragma unroll
        for (int ks = 0; ks < 4; ks++) {
            #pragma unroll
            for (int j2 = 0; j2 < 4; j2++) {
                int key = j2 * 16 + r8 + ((lane >> 4) & 1) * 8;
                int col = ks * 16 + ((lane >> 3) & 1) * 8;
                uint32_t bf4[4];
                ldsm4(bf4, kb + key * 144 + col * 2);
                mma16(sc[2*j2],   qf[ks], &bf4[0]);
                mma16(sc[2*j2+1], qf[ks], &bf4[2]);
            }
        }

        // ---- online softmax ----
        const float scale = 0.125f;
        float mx0 = -1e30f, mx1 = -1e30f;
        #pragma unroll
        for (int j = 0; j < 8; j++) {
            sc[j][0] *= scale; sc[j][1] *= scale;
            sc[j][2] *= scale; sc[j][3] *= scale;
            mx0 = fmaxf(mx0, fmaxf(sc[j][0], sc[j][1]));
            mx1 = fmaxf(mx1, fmaxf(sc[j][2], sc[j][3]));
        }
        mx0 = fmaxf(mx0, __shfl_xor_sync(0xffffffffu, mx0, 1));
        mx0 = fmaxf(mx0, __shfl_xor_sync(0xffffffffu, mx0, 2));
        mx1 = fmaxf(mx1, __shfl_xor_sync(0xffffffffu, mx1, 1));
        mx1 = fmaxf(mx1, __shfl_xor_sync(0xffffffffu, mx1, 2));
        float nm0 = fmaxf(m0, mx0), nm1 = fmaxf(m1, mx1);
        float c0 = __expf(m0 - nm0), c1 = __expf(m1 - nm1);
        m0 = nm0; m1 = nm1;
        l0 *= c0; l1 *= c1;
        #pragma unroll
        for (int j = 0; j < 8; j++) {
            o[j][0] *= c0; o[j][1] *= c0;
            o[j][2] *= c1; o[j][3] *= c1;
        }
        #pragma unroll
        for (int j = 0; j < 8; j++) {
            float p0 = __expf(sc[j][0] - m0); sc[j][0] = p0; l0 += p0;
            float p1 = __expf(sc[j][1] - m0); sc[j][1] = p1; l0 += p1;
            float p2 = __expf(sc[j][2] - m1); sc[j][2] = p2; l1 += p2;
            float p3 = __expf(sc[j][3] - m1); sc[j][3] = p3; l1 += p3;
        }

        // ---- O += P @ V ----
        #pragma unroll
        for (int kt = 0; kt < 4; kt++) {
            int ja = 2 * kt, jb = 2 * kt + 1;
            uint32_t pa[4];
            pa[0] = pack2h(sc[ja][0], sc[ja][1]);
            pa[1] = pack2h(sc[ja][2], sc[ja][3]);
            pa[2] = pack2h(sc[jb][0], sc[jb][1]);
            pa[3] = pack2h(sc[jb][2], sc[jb][3]);
            #pragma unroll
            for (int jn2 = 0; jn2 < 4; jn2++) {
                int key = kt * 16 + r8 + ((lane >> 3) & 1) * 8;
                int col = jn2 * 16 + ((lane >> 4) & 1) * 8;
                uint32_t vf4[4];
                ldsm4t(vf4, vb + key * 144 + col * 2);
                mma16(o[2*jn2],   pa, &vf4[0]);
                mma16(o[2*jn2+1], pa, &vf4[2]);
            }
        }
        __syncthreads();
    }

    // ---- finalize ----
    l0 += __shfl_xor_sync(0xffffffffu, l0, 1);
    l0 += __shfl_xor_sync(0xffffffffu, l0, 2);
    l1 += __shfl_xor_sync(0xffffffffu, l1, 1);
    l1 += __shfl_xor_sync(0xffffffffu, l1, 2);
    float inv0 = 1.0f / l0, inv1 = 1.0f / l1;

    int row0 = blockIdx.x * 128 + warp * 16 + g;
    size_t base0 = ((size_t)b * S_ + row0) * D_ + h * HD_;
    size_t base1 = base0 + (size_t)8 * D_;
    #pragma unroll
    for (int j = 0; j < 8; j++) {
        int col = j * 8 + tg * 2;
        ushort2 w0, w1;
        w0.x = f2h(o[j][0] * inv0); w0.y = f2h(o[j][1] * inv0);
        w1.x = f2h(o[j][2] * inv1); w1.y = f2h(o[j][3] * inv1);
        *(ushort2*)(avp + base0 + col) = w0;
        *(ushort2*)(avp + base1 + col) = w1;
    }
}

// ---------------------------------------------------------------------------
// Launch
// ---------------------------------------------------------------------------
extern "C" void kernel_launch(void* const* d_in, const int* in_sizes, int n_in,
                              void* d_out, int out_size)
{
    const float* x          = (const float*)d_in[0];
    const float* pns        = (const float*)d_in[1];
    const float* w_mlp_in   = (const float*)d_in[2];
    const float* wq         = (const float*)d_in[3];
    const float* wk         = (const float*)d_in[4];
    const float* wv         = (const float*)d_in[5];
    const float* w_mlp_out  = (const float*)d_in[6];
    const float* b_mlp_out  = (const float*)d_in[7];
    const float* w_attn_out = (const float*)d_in[8];
    const float* b_attn_out = (const float*)d_in[9];
    float* out = (float*)d_out;

    uint16_t *xn, *hbuf, *av, *q, *k, *v;
    uint16_t *w1, *wqp, *wkp, *wvp, *w2, *wo;
    cudaGetSymbolAddress((void**)&xn,  g_xn);
    cudaGetSymbolAddress((void**)&hbuf, g_h);
    cudaGetSymbolAddress((void**)&av,  g_av);
    cudaGetSymbolAddress((void**)&q,   g_q);
    cudaGetSymbolAddress((void**)&k,   g_k);
    cudaGetSymbolAddress((void**)&v,   g_v);
    cudaGetSymbolAddress((void**)&w1,  g_w1);
    cudaGetSymbolAddress((void**)&wqp, g_wq);
    cudaGetSymbolAddress((void**)&wkp, g_wk);
    cudaGetSymbolAddress((void**)&wvp, g_wv);
    cudaGetSymbolAddress((void**)&w2,  g_w2);
    cudaGetSymbolAddress((void**)&wo,  g_wo);

    cudaFuncSetAttribute(fattn_kernel, cudaFuncAttributeMaxDynamicSharedMemorySize, AT_SMEM);

    // 0. weight converts
    const int DM = D_ * MLP_, DD = D_ * D_;
    cvt_kernel<<<DM / 1024, 256>>>(w_mlp_in,   w1,  DM);
    cvt_kernel<<<DD / 1024, 256>>>(wq,         wqp, DD);
    cvt_kernel<<<DD / 1024, 256>>>(wk,         wkp, DD);
    cvt_kernel<<<DD / 1024, 256>>>(wv,         wvp, DD);
    cvt_kernel<<<DM / 1024, 256>>>(w_mlp_out,  w2,  DM);
    cvt_kernel<<<DD / 1024, 256>>>(w_attn_out, wo,  DD);

    // 1. RMSNorm -> xn fp16
    rmsnorm_kernel<<<MROWS, 256>>>(x, pns, xn);

    // 2. h = gelu(xn @ w_mlp_in) -> fp16
    dim3 g_mlp(MLP_ / 128, MROWS / 128);
    hgemm_kernel<1><<<g_mlp, 256>>>(xn, w1, nullptr, hbuf,
                                    nullptr, nullptr, nullptr,
                                    MROWS, MLP_, D_);

    // 3. q/k/v = xn @ w{q,k,v} -> fp16
    dim3 g_d(D_ / 128, MROWS / 128);
    hgemm_kernel<4><<<g_d, 256>>>(xn, wqp, nullptr, q,
                                  nullptr, nullptr, nullptr, MROWS, D_, D_);
    hgemm_kernel<4><<<g_d, 256>>>(xn, wkp, nullptr, k,
                                  nullptr, nullptr, nullptr, MROWS, D_, D_);
    hgemm_kernel<4><<<g_d, 256>>>(xn, wvp, nullptr, v,
                                  nullptr, nullptr, nullptr, MROWS, D_, D_);

    // 4. flash attention -> av fp16
    dim3 g_attn(S_ / 128, H_, B_);
    fattn_kernel<<<g_attn, 256, AT_SMEM>>>(q, k, v, av);

    // 5. out = resid + h @ w_mlp_out + b_mlp_out + b_attn_out
    hgemm_kernel<2><<<g_d, 256>>>(hbuf, w2, out, nullptr,
                                  b_mlp_out, b_attn_out, x, MROWS, D_, MLP_);

    // 6. out += av @ w_attn_out
    hgemm_kernel<3><<<g_d, 256>>>(av, wo, out, nullptr,
                                  nullptr, nullptr, nullptr, MROWS, D_, D_);
}

// round 15
// speedup vs baseline: 7.7743x; 1.1897x over previous
#include <cuda_runtime.h>
#include <cuda_fp16.h>
#include <cstdint>

#define B_    4
#define S_    2048
#define D_    1024
#define H_    16
#define HD_   64
#define MLP_  4096
#define MROWS (B_*S_)   // 8192
#define QKV_LD 3072     // fused q|k|v row stride
#define HAV_LD 5120     // fused h|av row stride (K of final GEMM)

// ---------------------------------------------------------------------------
// Scratch (device globals) — fp16 activations & weights.
// ---------------------------------------------------------------------------
__device__ __align__(16) uint16_t g_xn  [(size_t)MROWS * D_];
__device__ __align__(16) uint16_t g_qkv [(size_t)MROWS * QKV_LD];
__device__ __align__(16) uint16_t g_hav [(size_t)MROWS * HAV_LD];
__device__ __align__(16) uint16_t g_w1  [(size_t)D_ * MLP_];
__device__ __align__(16) uint16_t g_wqkv[(size_t)D_ * QKV_LD];
__device__ __align__(16) uint16_t g_w2  [(size_t)HAV_LD * D_];   // [w_mlp_out ; w_attn_out]

// ---------------------------------------------------------------------------
// Scalar helpers
// ---------------------------------------------------------------------------
__device__ __forceinline__ uint16_t f2h(float v) {
    return __half_as_ushort(__float2half_rn(v));
}
__device__ __forceinline__ uint32_t pack2h(float a, float b) {
    return (uint32_t)f2h(a) | ((uint32_t)f2h(b) << 16);
}
__device__ __forceinline__ float gelu_tanh(float v) {
    float t = 0.7978845608028654f * (v + 0.044715f * v * v * v);
    return 0.5f * v * (1.0f + tanhf(t));
}

// ---------------------------------------------------------------------------
// PTX helpers
// ---------------------------------------------------------------------------
__device__ __forceinline__ void ldsm4(uint32_t* d, uint32_t a) {
    asm volatile("ldmatrix.sync.aligned.m8n8.x4.shared.b16 {%0,%1,%2,%3}, [%4];"
                 : "=r"(d[0]), "=r"(d[1]), "=r"(d[2]), "=r"(d[3]) : "r"(a));
}
__device__ __forceinline__ void ldsm4t(uint32_t* d, uint32_t a) {
    asm volatile("ldmatrix.sync.aligned.m8n8.x4.trans.shared.b16 {%0,%1,%2,%3}, [%4];"
                 : "=r"(d[0]), "=r"(d[1]), "=r"(d[2]), "=r"(d[3]) : "r"(a));
}
__device__ __forceinline__ void mma16(float* c, const uint32_t* a, const uint32_t* b) {
    asm volatile(
        "mma.sync.aligned.m16n8k16.row.col.f32.f16.f16.f32 "
        "{%0,%1,%2,%3}, {%4,%5,%6,%7}, {%8,%9}, {%0,%1,%2,%3};"
        : "+f"(c[0]), "+f"(c[1]), "+f"(c[2]), "+f"(c[3])
        : "r"(a[0]), "r"(a[1]), "r"(a[2]), "r"(a[3]), "r"(b[0]), "r"(b[1]));
}
__device__ __forceinline__ void cpa16(uint32_t smem, const void* g) {
    asm volatile("cp.async.cg.shared.global [%0], [%1], 16;" :: "r"(smem), "l"(g));
}
#define CP_COMMIT() asm volatile("cp.async.commit_group;")

// ---------------------------------------------------------------------------
// fp32 -> fp16 converts
// ---------------------------------------------------------------------------
__global__ __launch_bounds__(256) void cvt_kernel(
    const float* __restrict__ src, uint16_t* __restrict__ dst, int n)
{
    int i = (blockIdx.x * 256 + threadIdx.x) * 4;
    if (i >= n) return;
    float4 v = *(const float4*)(src + i);
    ushort4 o;
    o.x = f2h(v.x); o.y = f2h(v.y); o.z = f2h(v.z); o.w = f2h(v.w);
    *(ushort4*)(dst + i) = o;
}

// src [D_][D_] -> dst columns [cofs, cofs+D_) of [D_][QKV_LD]
__global__ __launch_bounds__(256) void cvtq_kernel(
    const float* __restrict__ src, uint16_t* __restrict__ dst, int cofs)
{
    int i = (blockIdx.x * 256 + threadIdx.x) * 4;
    int k = i >> 10, n = i & 1023;
    float4 v = *(const float4*)(src + i);
    ushort4 o;
    o.x = f2h(v.x); o.y = f2h(v.y); o.z = f2h(v.z); o.w = f2h(v.w);
    *(ushort4*)(dst + (size_t)k * QKV_LD + cofs + n) = o;
}

// ---------------------------------------------------------------------------
// RMSNorm -> fp16
// ---------------------------------------------------------------------------
__global__ __launch_bounds__(256) void rmsnorm_kernel(
    const float* __restrict__ x, const float* __restrict__ scale,
    uint16_t* __restrict__ o)
{
    int row = blockIdx.x;
    const float4* xr = (const float4*)(x + (size_t)row * D_);
    float4 v = xr[threadIdx.x];
    float s = v.x*v.x + v.y*v.y + v.z*v.z + v.w*v.w;

    __shared__ float red[256];
    red[threadIdx.x] = s;
    __syncthreads();
    #pragma unroll
    for (int off = 128; off > 0; off >>= 1) {
        if (threadIdx.x < off) red[threadIdx.x] += red[threadIdx.x + off];
        __syncthreads();
    }
    float inv = rsqrtf(red[0] * (1.0f / D_) + 1e-6f);

    float4 sc = ((const float4*)scale)[threadIdx.x];
    ushort4 out;
    out.x = f2h(v.x * inv * sc.x);
    out.y = f2h(v.y * inv * sc.y);
    out.z = f2h(v.z * inv * sc.z);
    out.w = f2h(v.w * inv * sc.w);
    *(ushort4*)(o + (size_t)row * D_ + threadIdx.x * 4) = out;
}

// ---------------------------------------------------------------------------
// fp16 GEMM, cp.async 3-stage pipeline. 128x128 tile, BK=16, 256 thr,
// 8 warps 4(m)x2(n), warp = 32x64. A smem [m][k] stride 24; B smem [k][n]
// stride 136 — ldmatrix conflict-free (validated R9/R14 mapping).
// EPI: 1 gelu->fp16 (ldch), 2 +b1+b2+resid f32, 4 fp16 (ldch)
// ---------------------------------------------------------------------------
template<int EPI>
__global__ __launch_bounds__(256, 2) void hgemm_kernel(
    const uint16_t* __restrict__ A, const uint16_t* __restrict__ Bm,
    float* __restrict__ C, uint16_t* __restrict__ Ch, int ldch,
    const float* __restrict__ bias1, const float* __restrict__ bias2,
    const float* __restrict__ resid,
    int M, int N, int K)
{
    __shared__ __align__(16) uint16_t As[3][128][24];
    __shared__ __align__(16) uint16_t Bs[3][16][136];

    int tid = threadIdx.x;
    int bm = blockIdx.y, bn = blockIdx.x;
    int warp = tid >> 5, lane = tid & 31;
    int wm = (warp & 3) * 32;
    int wn = (warp >> 2) * 64;
    int g = lane >> 2, tg = lane & 3;

    int arow = tid >> 1, ak0 = (tid & 1) * 8;   // A: 1 uint4/thread/stage
    int bkr  = tid >> 4, bnc = (tid & 15) * 8;  // B: 1 uint4/thread/stage

    const uint16_t* pA = A  + (size_t)(bm * 128 + arow) * K + ak0;
    const uint16_t* pB = Bm + (size_t)bkr * N + bn * 128 + bnc;

    int sub = lane >> 3, r8 = lane & 7;
    int a_lane_off = (((sub & 1) * 8 + r8) * 24 + (sub >> 1) * 8) * 2;
    int b_lane_off = (((sub & 1) * 8 + r8) * 136 + (sub >> 1) * 8) * 2;

    uint32_t sA = (uint32_t)__cvta_generic_to_shared(&As[0][0][0]);
    uint32_t sB = (uint32_t)__cvta_generic_to_shared(&Bs[0][0][0]);
    const int A_ST = 128 * 24 * 2;   // 6144 B / stage
    const int B_ST = 16 * 136 * 2;   // 4352 B / stage
    uint32_t aDst = sA + arow * 48 + ak0 * 2;
    uint32_t bDst = sB + bkr * 272 + bnc * 2;

    float acc[2][8][4];
    #pragma unroll
    for (int i = 0; i < 2; i++)
        #pragma unroll
        for (int j = 0; j < 8; j++)
            #pragma unroll
            for (int r = 0; r < 4; r++) acc[i][j][r] = 0.0f;

    int NK = K >> 4;
    // prologue: stages 0, 1
    cpa16(aDst,        pA);
    cpa16(bDst,        pB);
    CP_COMMIT();
    cpa16(aDst + A_ST, pA + 16);
    cpa16(bDst + B_ST, pB + (size_t)16 * N);
    CP_COMMIT();

    for (int it = 0; it < NK; it++) {
        asm volatile("cp.async.wait_group 1;" ::: "memory");
        __syncthreads();

        // prefetch stage it+2 (overlaps MMA below); empty commit keeps count
        if (it + 2 < NK) {
            int s2 = (it + 2) % 3;
            int k2 = (it + 2) * 16;
            cpa16(aDst + s2 * A_ST, pA + k2);
            cpa16(bDst + s2 * B_ST, pB + (size_t)k2 * N);
        }
        CP_COMMIT();

        int s = it % 3;
        uint32_t af[2][4];
        #pragma unroll
        for (int i = 0; i < 2; i++) {
            int m0 = wm + i * 16;
            ldsm4(af[i], sA + s * A_ST + m0 * 48 + a_lane_off);
        }
        #pragma unroll
        for (int jj = 0; jj < 4; jj++) {
            int n0 = wn + jj * 16;
            uint32_t bf4[4];
            ldsm4t(bf4, sB + s * B_ST + n0 * 2 + b_lane_off);
            #pragma unroll
            for (int hf = 0; hf < 2; hf++) {
                int j = jj * 2 + hf;
                #pragma unroll
                for (int i = 0; i < 2; i++)
                    mma16(acc[i][j], af[i], bf4 + hf * 2);
            }
        }
        __syncthreads();
    }

    #pragma unroll
    for (int i = 0; i < 2; i++) {
        #pragma unroll
        for (int j = 0; j < 8; j++) {
            int row0 = bm * 128 + wm + i * 16 + g;
            int col  = bn * 128 + wn + j * 8 + tg * 2;
            #pragma unroll
            for (int rr = 0; rr < 2; rr++) {
                int row = row0 + rr * 8;
                float v0 = acc[i][j][rr * 2 + 0];
                float v1 = acc[i][j][rr * 2 + 1];
                if (EPI == 1 || EPI == 4) {
                    if (EPI == 1) { v0 = gelu_tanh(v0); v1 = gelu_tanh(v1); }
                    ushort2 o;
                    o.x = f2h(v0); o.y = f2h(v1);
                    *(ushort2*)(Ch + (size_t)row * ldch + col) = o;
                } else {
                    size_t idx = (size_t)row * N + col;
                    v0 += bias1[col] + bias2[col] + resid[idx];
                    v1 += bias1[col + 1] + bias2[col + 1] + resid[idx + 1];
                    C[idx]     = v0;
                    C[idx + 1] = v1;
                }
            }
        }
    }
}

// ---------------------------------------------------------------------------
// fp16 flash attention. Grid (S/128, H, B), 256 thr = 8 warps, 16 q-rows per
// warp. Reads q/k/v from fused [M][QKV_LD]; writes av into fused hav buffer.
// K/V tiles (64 keys) double-buffered via cp.async; row stride 72 fp16.
// ---------------------------------------------------------------------------
#define AT_BUF   9216u           // one 64x72 fp16 buffer, bytes
#define AT_STAGE (2u * AT_BUF)   // K, V
#define AT_SMEM  (2u * AT_STAGE) // 36864 bytes

__global__ __launch_bounds__(256) void fattn_kernel(
    const uint16_t* __restrict__ qkv, uint16_t* __restrict__ hav)
{
    extern __shared__ __align__(16) uint16_t sm[];
    int h = blockIdx.y, b = blockIdx.z;
    int tid = threadIdx.x, warp = tid >> 5, lane = tid & 31;
    int g = lane >> 2, tg = lane & 3, r8 = lane & 7;
    uint32_t smb = (uint32_t)__cvta_generic_to_shared(sm);

    // ---- stage Q (aliases stage area), load ldmatrix fragments ----
    {
        int row = tid >> 1;
        int half = (tid & 1) * 32;
        size_t gq = ((size_t)b * S_ + blockIdx.x * 128 + row) * QKV_LD + h * HD_ + half;
        #pragma unroll
        for (int i = 0; i < 4; i++)
            *(uint4*)(sm + row * 72 + half + i * 8) = *(const uint4*)(qkv + gq + i * 8);
    }
    __syncthreads();
    uint32_t qf[4][4];
    {
        int qr = warp * 16 + r8 + ((lane >> 3) & 1) * 8;
        #pragma unroll
        for (int ks = 0; ks < 4; ks++) {
            int col = ks * 16 + ((lane >> 4) & 1) * 8;
            ldsm4(qf[ks], smb + (qr * 72 + col) * 2);
        }
    }
    __syncthreads();

    // cp.async loader: 2 threads per row; buf 0 = K (+D_), buf 1 = V (+2*D_)
    int buf = tid >> 7;
    int u   = (tid & 127) >> 1;
    int hc  = (tid & 1) * 64;
    const uint16_t* gsrc = qkv + ((size_t)b * S_ + u) * QKV_LD +
                           (buf + 1) * D_ + h * HD_ + (tid & 1) * 32;
    uint32_t sdst = smb + buf * AT_BUF + u * 144 + hc;

    float o[8][4];
    #pragma unroll
    for (int j = 0; j < 8; j++)
        #pragma unroll
        for (int r = 0; r < 4; r++) o[j][r] = 0.0f;
    float m0 = -1e30f, m1 = -1e30f, l0 = 0.0f, l1 = 0.0f;

    {
        #pragma unroll
        for (int i = 0; i < 4; i++) cpa16(sdst + i * 16, gsrc + i * 8);
        CP_COMMIT();
    }

    for (int it = 0; it < S_ / 64; it++) {
        if (it + 1 < S_ / 64) {
            const uint16_t* src = gsrc + (size_t)(it + 1) * 64 * QKV_LD;
            uint32_t dst = sdst + ((it + 1) & 1) * AT_STAGE;
            #pragma unroll
            for (int i = 0; i < 4; i++) cpa16(dst + i * 16, src + i * 8);
            CP_COMMIT();
            asm volatile("cp.async.wait_group 1;");
        } else {
            asm volatile("cp.async.wait_group 0;");
        }
        __syncthreads();

        uint32_t kb = smb + (it & 1) * AT_STAGE;
        uint32_t vb = kb + AT_BUF;

        float sc[8][4];
        #pragma unroll
        for (int j = 0; j < 8; j++)
            #pragma unroll
            for (int r = 0; r < 4; r++) sc[j][r] = 0.0f;

        #pragma unroll
        for (int ks = 0; ks < 4; ks++) {
            #pragma unroll
            for (int j2 = 0; j2 < 4; j2++) {
                int key = j2 * 16 + r8 + ((lane >> 4) & 1) * 8;
                int col = ks * 16 + ((lane >> 3) & 1) * 8;
                uint32_t bf4[4];
                ldsm4(bf4, kb + key * 144 + col * 2);
                mma16(sc[2*j2],   qf[ks], &bf4[0]);
                mma16(sc[2*j2+1], qf[ks], &bf4[2]);
            }
        }

        const float scale = 0.125f;
        float mx0 = -1e30f, mx1 = -1e30f;
        #pragma unroll
        for (int j = 0; j < 8; j++) {
            sc[j][0] *= scale; sc[j][1] *= scale;
            sc[j][2] *= scale; sc[j][3] *= scale;
            mx0 = fmaxf(mx0, fmaxf(sc[j][0], sc[j][1]));
            mx1 = fmaxf(mx1, fmaxf(sc[j][2], sc[j][3]));
        }
        mx0 = fmaxf(mx0, __shfl_xor_sync(0xffffffffu, mx0, 1));
        mx0 = fmaxf(mx0, __shfl_xor_sync(0xffffffffu, mx0, 2));
        mx1 = fmaxf(mx1, __shfl_xor_sync(0xffffffffu, mx1, 1));
        mx1 = fmaxf(mx1, __shfl_xor_sync(0xffffffffu, mx1, 2));
        float nm0 = fmaxf(m0, mx0), nm1 = fmaxf(m1, mx1);
        float c0 = __expf(m0 - nm0), c1 = __expf(m1 - nm1);
        m0 = nm0; m1 = nm1;
        l0 *= c0; l1 *= c1;
        #pragma unroll
        for (int j = 0; j < 8; j++) {
            o[j][0] *= c0; o[j][1] *= c0;
            o[j][2] *= c1; o[j][3] *= c1;
        }
        #pragma unroll
        for (int j = 0; j < 8; j++) {
            float p0 = __expf(sc[j][0] - m0); sc[j][0] = p0; l0 += p0;
            float p1 = __expf(sc[j][1] - m0); sc[j][1] = p1; l0 += p1;
            float p2 = __expf(sc[j][2] - m1); sc[j][2] = p2; l1 += p2;
            float p3 = __expf(sc[j][3] - m1); sc[j][3] = p3; l1 += p3;
        }

        #pragma unroll
        for (int kt = 0; kt < 4; kt++) {
            int ja = 2 * kt, jb = 2 * kt + 1;
            uint32_t pa[4];
            pa[0] = pack2h(sc[ja][0], sc[ja][1]);
            pa[1] = pack2h(sc[ja][2], sc[ja][3]);
            pa[2] = pack2h(sc[jb][0], sc[jb][1]);
            pa[3] = pack2h(sc[jb][2], sc[jb][3]);
            #pragma unroll
            for (int jn2 = 0; jn2 < 4; jn2++) {
                int key = kt * 16 + r8 + ((lane >> 3) & 1) * 8;
                int col = jn2 * 16 + ((lane >> 4) & 1) * 8;
                uint32_t vf4[4];
                ldsm4t(vf4, vb + key * 144 + col * 2);
                mma16(o[2*jn2],   pa, &vf4[0]);
                mma16(o[2*jn2+1], pa, &vf4[2]);
            }
        }
        __syncthreads();
    }

    l0 += __shfl_xor_sync(0xffffffffu, l0, 1);
    l0 += __shfl_xor_sync(0xffffffffu, l0, 2);
    l1 += __shfl_xor_sync(0xffffffffu, l1, 1);
    l1 += __shfl_xor_sync(0xffffffffu, l1, 2);
    float inv0 = 1.0f / l0, inv1 = 1.0f / l1;

    int row0 = blockIdx.x * 128 + warp * 16 + g;
    size_t base0 = ((size_t)b * S_ + row0) * HAV_LD + MLP_ + h * HD_;
    size_t base1 = base0 + (size_t)8 * HAV_LD;
    #pragma unroll
    for (int j = 0; j < 8; j++) {
        int col = j * 8 + tg * 2;
        ushort2 w0, w1;
        w0.x = f2h(o[j][0] * inv0); w0.y = f2h(o[j][1] * inv0);
        w1.x = f2h(o[j][2] * inv1); w1.y = f2h(o[j][3] * inv1);
        *(ushort2*)(hav + base0 + col) = w0;
        *(ushort2*)(hav + base1 + col) = w1;
    }
}

// ---------------------------------------------------------------------------
// Launch
// ---------------------------------------------------------------------------
extern "C" void kernel_launch(void* const* d_in, const int* in_sizes, int n_in,
                              void* d_out, int out_size)
{
    const float* x          = (const float*)d_in[0];
    const float* pns        = (const float*)d_in[1];
    const float* w_mlp_in   = (const float*)d_in[2];
    const float* wq         = (const float*)d_in[3];
    const float* wk         = (const float*)d_in[4];
    const float* wv         = (const float*)d_in[5];
    const float* w_mlp_out  = (const float*)d_in[6];
    const float* b_mlp_out  = (const float*)d_in[7];
    const float* w_attn_out = (const float*)d_in[8];
    const float* b_attn_out = (const float*)d_in[9];
    float* out = (float*)d_out;

    uint16_t *xn, *qkv, *hav, *w1, *wqkv, *w2;
    cudaGetSymbolAddress((void**)&xn,   g_xn);
    cudaGetSymbolAddress((void**)&qkv,  g_qkv);
    cudaGetSymbolAddress((void**)&hav,  g_hav);
    cudaGetSymbolAddress((void**)&w1,   g_w1);
    cudaGetSymbolAddress((void**)&wqkv, g_wqkv);
    cudaGetSymbolAddress((void**)&w2,   g_w2);

    cudaFuncSetAttribute(fattn_kernel, cudaFuncAttributeMaxDynamicSharedMemorySize, AT_SMEM);

    // 0. weight converts
    const int DM = D_ * MLP_, DD = D_ * D_;
    cvt_kernel<<<DM / 1024, 256>>>(w_mlp_in, w1, DM);
    cvtq_kernel<<<DD / 1024, 256>>>(wq, wqkv, 0);
    cvtq_kernel<<<DD / 1024, 256>>>(wk, wqkv, D_);
    cvtq_kernel<<<DD / 1024, 256>>>(wv, wqkv, 2 * D_);
    cvt_kernel<<<DM / 1024, 256>>>(w_mlp_out,  w2, DM);                 // rows 0..4095
    cvt_kernel<<<DD / 1024, 256>>>(w_attn_out, w2 + (size_t)MLP_ * D_, DD); // rows 4096..5119

    // 1. RMSNorm -> xn fp16
    rmsnorm_kernel<<<MROWS, 256>>>(x, pns, xn);

    // 2. h = gelu(xn @ w_mlp_in) -> hav cols [0, 4096)
    dim3 g_mlp(MLP_ / 128, MROWS / 128);
    hgemm_kernel<1><<<g_mlp, 256>>>(xn, w1, nullptr, hav, HAV_LD,
                                    nullptr, nullptr, nullptr,
                                    MROWS, MLP_, D_);

    // 3. qkv = xn @ [wq|wk|wv]  (one fused GEMM, N = 3072)
    dim3 g_qkv(QKV_LD / 128, MROWS / 128);
    hgemm_kernel<4><<<g_qkv, 256>>>(xn, wqkv, nullptr, qkv, QKV_LD,
                                    nullptr, nullptr, nullptr,
                                    MROWS, QKV_LD, D_);

    // 4. flash attention -> hav cols [4096, 5120)
    dim3 g_attn(S_ / 128, H_, B_);
    fattn_kernel<<<g_attn, 256, AT_SMEM>>>(qkv, hav);

    // 5. out = resid + [h|av] @ [w_mlp_out; w_attn_out] + b_mlp + b_attn
    dim3 g_out(D_ / 128, MROWS / 128);
    hgemm_kernel<2><<<g_out, 256>>>(hav, w2, out, nullptr, 0,
                                    b_mlp_out, b_attn_out, x,
                                    MROWS, D_, HAV_LD);
}